// round 1
// baseline (speedup 1.0000x reference)
#include <cuda_runtime.h>
#include <math.h>

#define N_NODES 100000
#define N_EDGES 1600000
#define NFEAT   512
#define HIDDEN  128
#define NCLASS  40

// ---------------- scratch (device globals; no allocation allowed) ----------
__device__ float g_support1[(long)N_NODES * HIDDEN];   // X @ W1
__device__ float g_h1[(long)N_NODES * HIDDEN];         // relu(agg + b1)
__device__ float g_support2[(long)N_NODES * NCLASS];   // h1 @ W2
__device__ int   g_deg[N_NODES];
__device__ int   g_row_ptr[N_NODES + 1];
__device__ int   g_cursor[N_NODES];
__device__ int   g_src_sorted[N_EDGES];
__device__ float g_val_sorted[N_EDGES];

// ---------------- CSR build --------------------------------------------------
__global__ void zero_deg_kernel() {
    int i = blockIdx.x * blockDim.x + threadIdx.x;
    if (i < N_NODES) g_deg[i] = 0;
}

__global__ void hist_kernel(const int* __restrict__ dst) {
    int i = blockIdx.x * blockDim.x + threadIdx.x;
    if (i < N_EDGES) atomicAdd(&g_deg[dst[i]], 1);
}

// single-block exclusive scan over g_deg -> g_row_ptr (and cursor copy)
__global__ void scan_kernel() {
    __shared__ int sh[1024];
    __shared__ int s_carry;
    if (threadIdx.x == 0) s_carry = 0;
    __syncthreads();
    for (int base = 0; base < N_NODES; base += 1024) {
        int i = base + threadIdx.x;
        int v = (i < N_NODES) ? g_deg[i] : 0;
        sh[threadIdx.x] = v;
        __syncthreads();
        for (int off = 1; off < 1024; off <<= 1) {
            int t = (threadIdx.x >= off) ? sh[threadIdx.x - off] : 0;
            __syncthreads();
            sh[threadIdx.x] += t;
            __syncthreads();
        }
        int excl = s_carry + sh[threadIdx.x] - v;
        if (i < N_NODES) { g_row_ptr[i] = excl; g_cursor[i] = excl; }
        __syncthreads();
        if (threadIdx.x == 0) s_carry += sh[1023];
        __syncthreads();
    }
    if (threadIdx.x == 0) g_row_ptr[N_NODES] = N_EDGES;
}

__global__ void scatter_kernel(const int* __restrict__ src,
                               const int* __restrict__ dst,
                               const float* __restrict__ val) {
    int i = blockIdx.x * blockDim.x + threadIdx.x;
    if (i < N_EDGES) {
        int d = dst[i];
        int p = atomicAdd(&g_cursor[d], 1);
        g_src_sorted[p] = src[i];
        g_val_sorted[p] = val[i];
    }
}

// ---------------- GEMM1: support1 = X[100000,512] @ W1[512,128] -------------
#define BM 128
#define BN 128
#define BK 16
#define TM 8
#define TN 8

__global__ __launch_bounds__(256) void gemm1_kernel(const float* __restrict__ A,
                                                    const float* __restrict__ B) {
    __shared__ float As[BK][BM];
    __shared__ float Bs[BK][BN];
    int tid = threadIdx.x;
    int block_row = blockIdx.x * BM;
    int tx = tid % 16;   // col-thread
    int ty = tid / 16;   // row-thread
    float acc[TM][TN];
#pragma unroll
    for (int i = 0; i < TM; i++)
#pragma unroll
        for (int j = 0; j < TN; j++) acc[i][j] = 0.f;

    int a_row = tid >> 2;            // 0..63
    int a_col = (tid & 3) * 4;       // 0,4,8,12
    int b_row = tid >> 5;            // 0..7
    int b_col = (tid & 31) * 4;

    for (int k0 = 0; k0 < NFEAT; k0 += BK) {
#pragma unroll
        for (int i = 0; i < 2; i++) {
            int r = a_row + i * 64;
            int gr = block_row + r;
            float4 v = make_float4(0.f, 0.f, 0.f, 0.f);
            if (gr < N_NODES)
                v = *(const float4*)&A[(long)gr * NFEAT + k0 + a_col];
            As[a_col + 0][r] = v.x;
            As[a_col + 1][r] = v.y;
            As[a_col + 2][r] = v.z;
            As[a_col + 3][r] = v.w;
        }
#pragma unroll
        for (int i = 0; i < 2; i++) {
            int r = b_row + i * 8;
            float4 v = *(const float4*)&B[(k0 + r) * HIDDEN + b_col];
            *(float4*)&Bs[r][b_col] = v;
        }
        __syncthreads();
#pragma unroll
        for (int k = 0; k < BK; k++) {
            float4 a0 = *(float4*)&As[k][ty * TM];
            float4 a1 = *(float4*)&As[k][ty * TM + 4];
            float4 b0 = *(float4*)&Bs[k][tx * TN];
            float4 b1 = *(float4*)&Bs[k][tx * TN + 4];
            float a[TM] = {a0.x, a0.y, a0.z, a0.w, a1.x, a1.y, a1.z, a1.w};
            float b[TN] = {b0.x, b0.y, b0.z, b0.w, b1.x, b1.y, b1.z, b1.w};
#pragma unroll
            for (int i = 0; i < TM; i++)
#pragma unroll
                for (int j = 0; j < TN; j++) acc[i][j] += a[i] * b[j];
        }
        __syncthreads();
    }
#pragma unroll
    for (int i = 0; i < TM; i++) {
        int gr = block_row + ty * TM + i;
        if (gr < N_NODES) {
#pragma unroll
            for (int j = 0; j < TN; j += 4) {
                float4 v = make_float4(acc[i][j], acc[i][j + 1], acc[i][j + 2], acc[i][j + 3]);
                *(float4*)&g_support1[(long)gr * HIDDEN + tx * TN + j] = v;
            }
        }
    }
}

// ---------------- SpMM1: h1 = relu(scatter_sum(support1[src]*val) + b1) -----
__global__ __launch_bounds__(256) void spmm1_kernel(const float* __restrict__ b1) {
    int warp = (blockIdx.x * blockDim.x + threadIdx.x) >> 5;
    int lane = threadIdx.x & 31;
    if (warp >= N_NODES) return;
    int beg = g_row_ptr[warp];
    int end = g_row_ptr[warp + 1];
    float4 acc = make_float4(0.f, 0.f, 0.f, 0.f);
    for (int e = beg; e < end; e++) {
        int   s = g_src_sorted[e];
        float v = g_val_sorted[e];
        float4 sup = *(const float4*)&g_support1[(long)s * HIDDEN + lane * 4];
        acc.x += v * sup.x; acc.y += v * sup.y;
        acc.z += v * sup.z; acc.w += v * sup.w;
    }
    float4 bb = *(const float4*)&b1[lane * 4];
    acc.x = fmaxf(acc.x + bb.x, 0.f);
    acc.y = fmaxf(acc.y + bb.y, 0.f);
    acc.z = fmaxf(acc.z + bb.z, 0.f);
    acc.w = fmaxf(acc.w + bb.w, 0.f);
    *(float4*)&g_h1[(long)warp * HIDDEN + lane * 4] = acc;
}

// ---------------- GEMM2: support2 = h1[100000,128] @ W2[128,40] -------------
// block: 128 rows x 40 cols, 256 threads, per-thread 4 rows x 5 cols
#define G2_SMEM (128 * 129 * 4 + 128 * 40 * 4)

__global__ __launch_bounds__(256) void gemm2_kernel(const float* __restrict__ W2) {
    extern __shared__ float sh[];
    float* shH = sh;               // [128][129] padded
    float* shW = sh + 128 * 129;   // [128][40]
    int tid = threadIdx.x;
    int row0 = blockIdx.x * 128;

    for (int i = tid; i < 128 * 32; i += 256) {
        int r = i >> 5, c4 = (i & 31) * 4;
        float4 v = make_float4(0.f, 0.f, 0.f, 0.f);
        if (row0 + r < N_NODES)
            v = *(const float4*)&g_h1[(long)(row0 + r) * HIDDEN + c4];
        shH[r * 129 + c4 + 0] = v.x;
        shH[r * 129 + c4 + 1] = v.y;
        shH[r * 129 + c4 + 2] = v.z;
        shH[r * 129 + c4 + 3] = v.w;
    }
    for (int i = tid; i < 128 * 40; i += 256) shW[i] = W2[i];
    __syncthreads();

    int tr = tid >> 3;          // 0..31
    int tc = (tid & 7) * 5;     // 0,5,...,35
    float acc[4][5];
#pragma unroll
    for (int i = 0; i < 4; i++)
#pragma unroll
        for (int j = 0; j < 5; j++) acc[i][j] = 0.f;

    for (int k = 0; k < 128; k++) {
        float a[4], b[5];
#pragma unroll
        for (int i = 0; i < 4; i++) a[i] = shH[(tr + 32 * i) * 129 + k];
#pragma unroll
        for (int j = 0; j < 5; j++) b[j] = shW[k * 40 + tc + j];
#pragma unroll
        for (int i = 0; i < 4; i++)
#pragma unroll
            for (int j = 0; j < 5; j++) acc[i][j] += a[i] * b[j];
    }
#pragma unroll
    for (int i = 0; i < 4; i++) {
        int r = row0 + tr + 32 * i;
        if (r < N_NODES) {
#pragma unroll
            for (int j = 0; j < 5; j++)
                g_support2[(long)r * NCLASS + tc + j] = acc[i][j];
        }
    }
}

// ---------------- SpMM2 + bias + log_softmax --------------------------------
__global__ __launch_bounds__(256) void spmm2_softmax_kernel(const float* __restrict__ b2,
                                                            float* __restrict__ out) {
    int warp = (blockIdx.x * blockDim.x + threadIdx.x) >> 5;
    int lane = threadIdx.x & 31;
    if (warp >= N_NODES) return;
    int beg = g_row_ptr[warp];
    int end = g_row_ptr[warp + 1];
    int  c0 = lane;
    int  c1 = lane + 32;
    bool has1 = (c1 < NCLASS);
    float a0 = 0.f, a1 = 0.f;
    for (int e = beg; e < end; e++) {
        int   s = g_src_sorted[e];
        float v = g_val_sorted[e];
        const float* row = &g_support2[(long)s * NCLASS];
        a0 += v * row[c0];
        if (has1) a1 += v * row[c1];
    }
    float z0 = a0 + b2[c0];
    float z1 = has1 ? (a1 + b2[c1]) : -INFINITY;
    float m = fmaxf(z0, z1);
#pragma unroll
    for (int off = 16; off > 0; off >>= 1)
        m = fmaxf(m, __shfl_xor_sync(0xFFFFFFFFu, m, off));
    float s = expf(z0 - m) + (has1 ? expf(z1 - m) : 0.f);
#pragma unroll
    for (int off = 16; off > 0; off >>= 1)
        s += __shfl_xor_sync(0xFFFFFFFFu, s, off);
    float L = m + logf(s);
    out[(long)warp * NCLASS + c0] = z0 - L;
    if (has1) out[(long)warp * NCLASS + c1] = z1 - L;
}

// ---------------- launch -----------------------------------------------------
extern "C" void kernel_launch(void* const* d_in, const int* in_sizes, int n_in,
                              void* d_out, int out_size) {
    const float* x        = (const float*)d_in[0];
    const int*   edge_src = (const int*)d_in[1];
    const int*   edge_dst = (const int*)d_in[2];
    const float* edge_val = (const float*)d_in[3];
    const float* W1       = (const float*)d_in[4];
    const float* b1       = (const float*)d_in[5];
    const float* W2       = (const float*)d_in[6];
    const float* b2       = (const float*)d_in[7];
    float* out = (float*)d_out;

    (void)in_sizes; (void)n_in; (void)out_size;

    cudaFuncSetAttribute(gemm2_kernel, cudaFuncAttributeMaxDynamicSharedMemorySize, G2_SMEM);

    // CSR build
    zero_deg_kernel<<<(N_NODES + 255) / 256, 256>>>();
    hist_kernel<<<(N_EDGES + 255) / 256, 256>>>(edge_dst);
    scan_kernel<<<1, 1024>>>();
    scatter_kernel<<<(N_EDGES + 255) / 256, 256>>>(edge_src, edge_dst, edge_val);

    // layer 1
    gemm1_kernel<<<(N_NODES + BM - 1) / BM, 256>>>(x, W1);
    spmm1_kernel<<<(N_NODES * 32 + 255) / 256, 256>>>(b1);

    // layer 2
    gemm2_kernel<<<(N_NODES + 127) / 128, 256, G2_SMEM>>>(W2);
    spmm2_softmax_kernel<<<(N_NODES * 32 + 255) / 256, 256>>>(b2, out);
}

// round 2
// speedup vs baseline: 1.3356x; 1.3356x over previous
#include <cuda_runtime.h>
#include <math.h>
#include <stdint.h>

#define N_NODES 100000
#define N_EDGES 1600000
#define NFEAT   512
#define HIDDEN  128
#define NCLASS  40

// ---------------- scratch (device globals; no allocation allowed) ----------
__device__ float g_support1[(long)N_NODES * HIDDEN];   // X @ W1
__device__ float g_h1[(long)N_NODES * HIDDEN];         // relu(agg + b1)
__device__ float g_support2[(long)N_NODES * NCLASS];   // h1 @ W2
__device__ int   g_deg[N_NODES];
__device__ int   g_row_ptr[N_NODES + 1];
__device__ int   g_cursor[N_NODES];
__device__ int   g_src_sorted[N_EDGES];
__device__ float g_val_sorted[N_EDGES];

// ---------------- CSR build --------------------------------------------------
__global__ void zero_deg_kernel() {
    int i = blockIdx.x * blockDim.x + threadIdx.x;
    if (i < N_NODES) g_deg[i] = 0;
}

__global__ void hist_kernel(const int* __restrict__ dst) {
    int i = blockIdx.x * blockDim.x + threadIdx.x;
    if (i < N_EDGES) atomicAdd(&g_deg[dst[i]], 1);
}

// single-block exclusive scan over g_deg -> g_row_ptr (and cursor copy)
__global__ void scan_kernel() {
    __shared__ int sh[1024];
    __shared__ int s_carry;
    if (threadIdx.x == 0) s_carry = 0;
    __syncthreads();
    for (int base = 0; base < N_NODES; base += 1024) {
        int i = base + threadIdx.x;
        int v = (i < N_NODES) ? g_deg[i] : 0;
        sh[threadIdx.x] = v;
        __syncthreads();
        for (int off = 1; off < 1024; off <<= 1) {
            int t = (threadIdx.x >= off) ? sh[threadIdx.x - off] : 0;
            __syncthreads();
            sh[threadIdx.x] += t;
            __syncthreads();
        }
        int excl = s_carry + sh[threadIdx.x] - v;
        if (i < N_NODES) { g_row_ptr[i] = excl; g_cursor[i] = excl; }
        __syncthreads();
        if (threadIdx.x == 0) s_carry += sh[1023];
        __syncthreads();
    }
    if (threadIdx.x == 0) g_row_ptr[N_NODES] = N_EDGES;
}

__global__ void scatter_kernel(const int* __restrict__ src,
                               const int* __restrict__ dst,
                               const float* __restrict__ val) {
    int i = blockIdx.x * blockDim.x + threadIdx.x;
    if (i < N_EDGES) {
        int d = dst[i];
        int p = atomicAdd(&g_cursor[d], 1);
        g_src_sorted[p] = src[i];
        g_val_sorted[p] = val[i];
    }
}

// ---------------- GEMM1 (tf32 tensor cores) ---------------------------------
// support1 = X[100000,512] @ W1[512,128]
// block tile 128x128, BK=32, 8 warps, warp tile 64x32, m16n8k8 tf32 mma.

#define G1_BM 128
#define G1_BK 32
#define AS_STRIDE 36    // bank = (4*row + col) % 32 -> conflict-free frag loads
#define BS_STRIDE 132   // bank = (4*t + g + 8*ni) % 32 -> conflict-free

__device__ __forceinline__ uint32_t f2tf32(float f) {
    uint32_t u;
    asm("cvt.rna.tf32.f32 %0, %1;" : "=r"(u) : "f"(f));
    return u;
}

__global__ __launch_bounds__(256, 2) void gemm1_tf32_kernel(const float* __restrict__ A,
                                                            const float* __restrict__ B) {
    __shared__ uint32_t As[G1_BM * AS_STRIDE];   // 128 rows x 32 (pad 36)
    __shared__ uint32_t Bs[G1_BK * BS_STRIDE];   // 32 rows x 128 (pad 132)

    const int tid  = threadIdx.x;
    const int warp = tid >> 5;
    const int lane = tid & 31;
    const int g = lane >> 2;      // 0..7
    const int t = lane & 3;       // 0..3
    const int wm = (warp >> 2) * 64;   // 0 or 64
    const int wn = (warp & 3) * 32;    // 0,32,64,96
    const int block_row = blockIdx.x * G1_BM;

    // global load mapping
    const int a_row = tid >> 1;             // 0..127
    const int a_col = (tid & 1) * 16;       // 0 or 16
    const int b_row = tid >> 3;             // 0..31
    const int b_col = (tid & 7) * 16;       // 0..112

    float acc[4][4][4];
#pragma unroll
    for (int mi = 0; mi < 4; mi++)
#pragma unroll
        for (int ni = 0; ni < 4; ni++)
#pragma unroll
            for (int q = 0; q < 4; q++) acc[mi][ni][q] = 0.f;

    for (int k0 = 0; k0 < NFEAT; k0 += G1_BK) {
        // ---- load A tile (guarded, cvt to tf32) ----
        {
            int gr = block_row + a_row;
            const float* src = &A[(long)gr * NFEAT + k0 + a_col];
#pragma unroll
            for (int i = 0; i < 4; i++) {
                float4 v = make_float4(0.f, 0.f, 0.f, 0.f);
                if (gr < N_NODES) v = *(const float4*)(src + i * 4);
                uint32_t* d = &As[a_row * AS_STRIDE + a_col + i * 4];
                d[0] = f2tf32(v.x); d[1] = f2tf32(v.y);
                d[2] = f2tf32(v.z); d[3] = f2tf32(v.w);
            }
        }
        // ---- load B tile ----
        {
            const float* src = &B[(long)(k0 + b_row) * HIDDEN + b_col];
#pragma unroll
            for (int i = 0; i < 4; i++) {
                float4 v = *(const float4*)(src + i * 4);
                uint32_t* d = &Bs[b_row * BS_STRIDE + b_col + i * 4];
                d[0] = f2tf32(v.x); d[1] = f2tf32(v.y);
                d[2] = f2tf32(v.z); d[3] = f2tf32(v.w);
            }
        }
        __syncthreads();

#pragma unroll
        for (int kk = 0; kk < 4; kk++) {
            const int kb = kk * 8;
            uint32_t af[4][4], bf[4][2];
#pragma unroll
            for (int mi = 0; mi < 4; mi++) {
                int r0 = wm + mi * 16 + g;
                af[mi][0] = As[(r0)     * AS_STRIDE + kb + t];
                af[mi][1] = As[(r0 + 8) * AS_STRIDE + kb + t];
                af[mi][2] = As[(r0)     * AS_STRIDE + kb + t + 4];
                af[mi][3] = As[(r0 + 8) * AS_STRIDE + kb + t + 4];
            }
#pragma unroll
            for (int ni = 0; ni < 4; ni++) {
                int c = wn + ni * 8 + g;
                bf[ni][0] = Bs[(kb + t)     * BS_STRIDE + c];
                bf[ni][1] = Bs[(kb + t + 4) * BS_STRIDE + c];
            }
#pragma unroll
            for (int mi = 0; mi < 4; mi++) {
#pragma unroll
                for (int ni = 0; ni < 4; ni++) {
                    asm volatile(
                        "mma.sync.aligned.m16n8k8.row.col.f32.tf32.tf32.f32 "
                        "{%0,%1,%2,%3}, {%4,%5,%6,%7}, {%8,%9}, {%0,%1,%2,%3};"
                        : "+f"(acc[mi][ni][0]), "+f"(acc[mi][ni][1]),
                          "+f"(acc[mi][ni][2]), "+f"(acc[mi][ni][3])
                        : "r"(af[mi][0]), "r"(af[mi][1]), "r"(af[mi][2]), "r"(af[mi][3]),
                          "r"(bf[ni][0]), "r"(bf[ni][1]));
                }
            }
        }
        __syncthreads();
    }

    // ---- store ----
#pragma unroll
    for (int mi = 0; mi < 4; mi++) {
        int r0 = block_row + wm + mi * 16 + g;
        int r1 = r0 + 8;
#pragma unroll
        for (int ni = 0; ni < 4; ni++) {
            int c = wn + ni * 8 + 2 * t;
            if (r0 < N_NODES)
                *(float2*)&g_support1[(long)r0 * HIDDEN + c] =
                    make_float2(acc[mi][ni][0], acc[mi][ni][1]);
            if (r1 < N_NODES)
                *(float2*)&g_support1[(long)r1 * HIDDEN + c] =
                    make_float2(acc[mi][ni][2], acc[mi][ni][3]);
        }
    }
}

// ---------------- SpMM1: h1 = relu(scatter_sum(support1[src]*val) + b1) -----
__global__ __launch_bounds__(256) void spmm1_kernel(const float* __restrict__ b1) {
    int warp = (blockIdx.x * blockDim.x + threadIdx.x) >> 5;
    int lane = threadIdx.x & 31;
    if (warp >= N_NODES) return;
    int beg = g_row_ptr[warp];
    int end = g_row_ptr[warp + 1];
    float4 acc = make_float4(0.f, 0.f, 0.f, 0.f);
    for (int e = beg; e < end; e++) {
        int   s = g_src_sorted[e];
        float v = g_val_sorted[e];
        float4 sup = *(const float4*)&g_support1[(long)s * HIDDEN + lane * 4];
        acc.x += v * sup.x; acc.y += v * sup.y;
        acc.z += v * sup.z; acc.w += v * sup.w;
    }
    float4 bb = *(const float4*)&b1[lane * 4];
    acc.x = fmaxf(acc.x + bb.x, 0.f);
    acc.y = fmaxf(acc.y + bb.y, 0.f);
    acc.z = fmaxf(acc.z + bb.z, 0.f);
    acc.w = fmaxf(acc.w + bb.w, 0.f);
    *(float4*)&g_h1[(long)warp * HIDDEN + lane * 4] = acc;
}

// ---------------- GEMM2: support2 = h1[100000,128] @ W2[128,40] -------------
#define G2_SMEM (128 * 129 * 4 + 128 * 40 * 4)

__global__ __launch_bounds__(256) void gemm2_kernel(const float* __restrict__ W2) {
    extern __shared__ float sh[];
    float* shH = sh;               // [128][129] padded
    float* shW = sh + 128 * 129;   // [128][40]
    int tid = threadIdx.x;
    int row0 = blockIdx.x * 128;

    for (int i = tid; i < 128 * 32; i += 256) {
        int r = i >> 5, c4 = (i & 31) * 4;
        float4 v = make_float4(0.f, 0.f, 0.f, 0.f);
        if (row0 + r < N_NODES)
            v = *(const float4*)&g_h1[(long)(row0 + r) * HIDDEN + c4];
        shH[r * 129 + c4 + 0] = v.x;
        shH[r * 129 + c4 + 1] = v.y;
        shH[r * 129 + c4 + 2] = v.z;
        shH[r * 129 + c4 + 3] = v.w;
    }
    for (int i = tid; i < 128 * 40; i += 256) shW[i] = W2[i];
    __syncthreads();

    int tr = tid >> 3;          // 0..31
    int tc = (tid & 7) * 5;     // 0,5,...,35
    float acc[4][5];
#pragma unroll
    for (int i = 0; i < 4; i++)
#pragma unroll
        for (int j = 0; j < 5; j++) acc[i][j] = 0.f;

    for (int k = 0; k < 128; k++) {
        float a[4], b[5];
#pragma unroll
        for (int i = 0; i < 4; i++) a[i] = shH[(tr + 32 * i) * 129 + k];
#pragma unroll
        for (int j = 0; j < 5; j++) b[j] = shW[k * 40 + tc + j];
#pragma unroll
        for (int i = 0; i < 4; i++)
#pragma unroll
            for (int j = 0; j < 5; j++) acc[i][j] += a[i] * b[j];
    }
#pragma unroll
    for (int i = 0; i < 4; i++) {
        int r = row0 + tr + 32 * i;
        if (r < N_NODES) {
#pragma unroll
            for (int j = 0; j < 5; j++)
                g_support2[(long)r * NCLASS + tc + j] = acc[i][j];
        }
    }
}

// ---------------- SpMM2 + bias + log_softmax --------------------------------
__global__ __launch_bounds__(256) void spmm2_softmax_kernel(const float* __restrict__ b2,
                                                            float* __restrict__ out) {
    int warp = (blockIdx.x * blockDim.x + threadIdx.x) >> 5;
    int lane = threadIdx.x & 31;
    if (warp >= N_NODES) return;
    int beg = g_row_ptr[warp];
    int end = g_row_ptr[warp + 1];
    int  c0 = lane;
    int  c1 = lane + 32;
    bool has1 = (c1 < NCLASS);
    float a0 = 0.f, a1 = 0.f;
    for (int e = beg; e < end; e++) {
        int   s = g_src_sorted[e];
        float v = g_val_sorted[e];
        const float* row = &g_support2[(long)s * NCLASS];
        a0 += v * row[c0];
        if (has1) a1 += v * row[c1];
    }
    float z0 = a0 + b2[c0];
    float z1 = has1 ? (a1 + b2[c1]) : -INFINITY;
    float m = fmaxf(z0, z1);
#pragma unroll
    for (int off = 16; off > 0; off >>= 1)
        m = fmaxf(m, __shfl_xor_sync(0xFFFFFFFFu, m, off));
    float s = expf(z0 - m) + (has1 ? expf(z1 - m) : 0.f);
#pragma unroll
    for (int off = 16; off > 0; off >>= 1)
        s += __shfl_xor_sync(0xFFFFFFFFu, s, off);
    float L = m + logf(s);
    out[(long)warp * NCLASS + c0] = z0 - L;
    if (has1) out[(long)warp * NCLASS + c1] = z1 - L;
}

// ---------------- launch -----------------------------------------------------
extern "C" void kernel_launch(void* const* d_in, const int* in_sizes, int n_in,
                              void* d_out, int out_size) {
    const float* x        = (const float*)d_in[0];
    const int*   edge_src = (const int*)d_in[1];
    const int*   edge_dst = (const int*)d_in[2];
    const float* edge_val = (const float*)d_in[3];
    const float* W1       = (const float*)d_in[4];
    const float* b1       = (const float*)d_in[5];
    const float* W2       = (const float*)d_in[6];
    const float* b2       = (const float*)d_in[7];
    float* out = (float*)d_out;

    (void)in_sizes; (void)n_in; (void)out_size;

    cudaFuncSetAttribute(gemm2_kernel, cudaFuncAttributeMaxDynamicSharedMemorySize, G2_SMEM);

    // CSR build
    zero_deg_kernel<<<(N_NODES + 255) / 256, 256>>>();
    hist_kernel<<<(N_EDGES + 255) / 256, 256>>>(edge_dst);
    scan_kernel<<<1, 1024>>>();
    scatter_kernel<<<(N_EDGES + 255) / 256, 256>>>(edge_src, edge_dst, edge_val);

    // layer 1
    gemm1_tf32_kernel<<<(N_NODES + G1_BM - 1) / G1_BM, 256>>>(x, W1);
    spmm1_kernel<<<(N_NODES * 32 + 255) / 256, 256>>>(b1);

    // layer 2
    gemm2_kernel<<<(N_NODES + 127) / 128, 256, G2_SMEM>>>(W2);
    spmm2_softmax_kernel<<<(N_NODES * 32 + 255) / 256, 256>>>(b2, out);
}

// round 3
// speedup vs baseline: 2.1634x; 1.6197x over previous
#include <cuda_runtime.h>
#include <math.h>
#include <stdint.h>

#define N_NODES 100000
#define N_EDGES 1600000
#define NFEAT   512
#define HIDDEN  128
#define NCLASS  40

// ---------------- scratch (device globals; no allocation allowed) ----------
__device__ float g_support1[(long)N_NODES * HIDDEN];   // X @ W1
__device__ float g_h1[(long)N_NODES * HIDDEN];         // relu(agg + b1)
__device__ float g_support2[(long)N_NODES * NCLASS];   // h1 @ W2
__device__ int   g_deg[N_NODES];
__device__ int   g_row_ptr[N_NODES + 1];
__device__ int   g_cursor[N_NODES];
__device__ int2  g_edges[N_EDGES];                     // {src, val bits}
__device__ int   g_psum[128];                          // block partial sums

#define SCAN_TILE 1024
#define N_SBLOCKS ((N_NODES + SCAN_TILE - 1) / SCAN_TILE)   // 98

// ---------------- CSR build --------------------------------------------------
__global__ void zero_deg_kernel() {
    int i = blockIdx.x * blockDim.x + threadIdx.x;
    if (i < N_NODES) g_deg[i] = 0;
}

__global__ void hist_kernel(const int* __restrict__ dst) {
    int i = blockIdx.x * blockDim.x + threadIdx.x;
    if (i < N_EDGES) atomicAdd(&g_deg[dst[i]], 1);
}

// phase 1: per-block (1024 elems) totals
__global__ __launch_bounds__(256) void scan_phase1() {
    int b = blockIdx.x, tid = threadIdx.x;
    int lane = tid & 31, warp = tid >> 5;
    int base = b * SCAN_TILE + tid * 4;
    int s = 0;
#pragma unroll
    for (int j = 0; j < 4; j++) {
        int i = base + j;
        if (i < N_NODES) s += g_deg[i];
    }
#pragma unroll
    for (int off = 16; off > 0; off >>= 1)
        s += __shfl_xor_sync(0xFFFFFFFFu, s, off);
    __shared__ int wsum[8];
    if (lane == 0) wsum[warp] = s;
    __syncthreads();
    if (tid == 0) {
        int t = 0;
#pragma unroll
        for (int w = 0; w < 8; w++) t += wsum[w];
        g_psum[b] = t;
    }
}

// phase 2: exclusive scan of 98 block totals (single block)
__global__ __launch_bounds__(128) void scan_phase2() {
    int tid = threadIdx.x;
    __shared__ int sh[128];
    int v = (tid < N_SBLOCKS) ? g_psum[tid] : 0;
    sh[tid] = v;
    __syncthreads();
#pragma unroll
    for (int off = 1; off < 128; off <<= 1) {
        int t = (tid >= off) ? sh[tid - off] : 0;
        __syncthreads();
        sh[tid] += t;
        __syncthreads();
    }
    if (tid < N_SBLOCKS) g_psum[tid] = sh[tid] - v;   // exclusive
}

// phase 3: local scan + block offset -> row_ptr, cursor
__global__ __launch_bounds__(256) void scan_phase3() {
    int b = blockIdx.x, tid = threadIdx.x;
    int lane = tid & 31, warp = tid >> 5;
    int base = b * SCAN_TILE + tid * 4;
    int v[4], tsum = 0;
#pragma unroll
    for (int j = 0; j < 4; j++) {
        int i = base + j;
        v[j] = (i < N_NODES) ? g_deg[i] : 0;
        tsum += v[j];
    }
    int incl = tsum;
#pragma unroll
    for (int off = 1; off < 32; off <<= 1) {
        int n = __shfl_up_sync(0xFFFFFFFFu, incl, off);
        if (lane >= off) incl += n;
    }
    __shared__ int wtot[8];
    if (lane == 31) wtot[warp] = incl;
    __syncthreads();
    if (warp == 0 && lane < 8) {
        int wv = wtot[lane];
        int wincl = wv;
#pragma unroll
        for (int off = 1; off < 8; off <<= 1) {
            int n = __shfl_up_sync(0xFFu, wincl, off);
            if (lane >= off) wincl += n;
        }
        wtot[lane] = wincl - wv;   // exclusive among warps
    }
    __syncthreads();
    int run = g_psum[b] + wtot[warp] + incl - tsum;
#pragma unroll
    for (int j = 0; j < 4; j++) {
        int i = base + j;
        if (i < N_NODES) { g_row_ptr[i] = run; g_cursor[i] = run; }
        run += v[j];
    }
    if (b == 0 && tid == 0) g_row_ptr[N_NODES] = N_EDGES;
}

__global__ void scatter_kernel(const int* __restrict__ src,
                               const int* __restrict__ dst,
                               const float* __restrict__ val) {
    int i = blockIdx.x * blockDim.x + threadIdx.x;
    if (i < N_EDGES) {
        int d = dst[i];
        int p = atomicAdd(&g_cursor[d], 1);
        g_edges[p] = make_int2(src[i], __float_as_int(val[i]));
    }
}

// ---------------- GEMM1 (tf32 tensor cores, cp.async double-buffered) -------
// support1 = X[100000,512] @ W1[512,128]
#define G1_BM 128
#define G1_BK 32
#define AS_STRIDE 36    // words; 144B rows -> 16B aligned chunks
#define BS_STRIDE 132   // words; 528B rows -> 16B aligned chunks
#define AS_WORDS (G1_BM * AS_STRIDE)   // 4608
#define BS_WORDS (G1_BK * BS_STRIDE)   // 4224
#define G1_SMEM ((2 * AS_WORDS + 2 * BS_WORDS) * 4)

__device__ __forceinline__ void cp16(uint32_t dst, const void* src, bool pred) {
    int sz = pred ? 16 : 0;
    asm volatile("cp.async.cg.shared.global [%0], [%1], 16, %2;\n"
                 :: "r"(dst), "l"(src), "r"(sz));
}

__global__ __launch_bounds__(256, 2) void gemm1_tf32_kernel(const float* __restrict__ A,
                                                            const float* __restrict__ B) {
    extern __shared__ uint32_t g1sh[];
    uint32_t* As = g1sh;                 // [2][AS_WORDS]
    uint32_t* Bs = g1sh + 2 * AS_WORDS;  // [2][BS_WORDS]
    const uint32_t smem_base = (uint32_t)__cvta_generic_to_shared(g1sh);

    const int tid  = threadIdx.x;
    const int warp = tid >> 5;
    const int lane = tid & 31;
    const int g = lane >> 2;           // 0..7
    const int t = lane & 3;            // 0..3
    const int wm = (warp >> 2) * 64;   // 0 or 64
    const int wn = (warp & 3) * 32;    // 0,32,64,96
    const int block_row = blockIdx.x * G1_BM;

    float acc[4][4][4];
#pragma unroll
    for (int mi = 0; mi < 4; mi++)
#pragma unroll
        for (int ni = 0; ni < 4; ni++)
#pragma unroll
            for (int q = 0; q < 4; q++) acc[mi][ni][q] = 0.f;

    // tile loader: A 128x32 (1024 16B-chunks), B 32x128 (1024 16B-chunks)
    auto load_tile = [&](int buf, int k0) {
#pragma unroll
        for (int j = 0; j < 4; j++) {
            int chunk = tid + j * 256;
            int row = chunk >> 3;
            int col = (chunk & 7) * 4;
            int gr = block_row + row;
            bool ok = gr < N_NODES;
            const float* src = A + (long)(ok ? gr : 0) * NFEAT + k0 + col;
            uint32_t dst = smem_base + (buf * AS_WORDS + row * AS_STRIDE + col) * 4;
            cp16(dst, src, ok);
        }
#pragma unroll
        for (int j = 0; j < 4; j++) {
            int chunk = tid + j * 256;
            int row = chunk >> 5;
            int col = (chunk & 31) * 4;
            const float* src = B + (long)(k0 + row) * HIDDEN + col;
            uint32_t dst = smem_base + (2 * AS_WORDS + buf * BS_WORDS + row * BS_STRIDE + col) * 4;
            cp16(dst, src, true);
        }
    };

    const int NT = NFEAT / G1_BK;   // 16
    load_tile(0, 0);
    asm volatile("cp.async.commit_group;\n");

    for (int kt = 0; kt < NT; kt++) {
        int buf = kt & 1;
        if (kt + 1 < NT) {
            load_tile(buf ^ 1, (kt + 1) * G1_BK);
            asm volatile("cp.async.commit_group;\n");
            asm volatile("cp.async.wait_group 1;\n");
        } else {
            asm volatile("cp.async.wait_group 0;\n");
        }
        __syncthreads();

        const uint32_t* Ab = As + buf * AS_WORDS;
        const uint32_t* Bb = Bs + buf * BS_WORDS;
#pragma unroll
        for (int kk = 0; kk < 4; kk++) {
            const int kb = kk * 8;
            uint32_t af[4][4], bf[4][2];
#pragma unroll
            for (int mi = 0; mi < 4; mi++) {
                int r0 = wm + mi * 16 + g;
                af[mi][0] = Ab[(r0)     * AS_STRIDE + kb + t];
                af[mi][1] = Ab[(r0 + 8) * AS_STRIDE + kb + t];
                af[mi][2] = Ab[(r0)     * AS_STRIDE + kb + t + 4];
                af[mi][3] = Ab[(r0 + 8) * AS_STRIDE + kb + t + 4];
            }
#pragma unroll
            for (int ni = 0; ni < 4; ni++) {
                int c = wn + ni * 8 + g;
                bf[ni][0] = Bb[(kb + t)     * BS_STRIDE + c];
                bf[ni][1] = Bb[(kb + t + 4) * BS_STRIDE + c];
            }
#pragma unroll
            for (int mi = 0; mi < 4; mi++) {
#pragma unroll
                for (int ni = 0; ni < 4; ni++) {
                    asm volatile(
                        "mma.sync.aligned.m16n8k8.row.col.f32.tf32.tf32.f32 "
                        "{%0,%1,%2,%3}, {%4,%5,%6,%7}, {%8,%9}, {%0,%1,%2,%3};"
                        : "+f"(acc[mi][ni][0]), "+f"(acc[mi][ni][1]),
                          "+f"(acc[mi][ni][2]), "+f"(acc[mi][ni][3])
                        : "r"(af[mi][0]), "r"(af[mi][1]), "r"(af[mi][2]), "r"(af[mi][3]),
                          "r"(bf[ni][0]), "r"(bf[ni][1]));
                }
            }
        }
        __syncthreads();
    }

#pragma unroll
    for (int mi = 0; mi < 4; mi++) {
        int r0 = block_row + wm + mi * 16 + g;
        int r1 = r0 + 8;
#pragma unroll
        for (int ni = 0; ni < 4; ni++) {
            int c = wn + ni * 8 + 2 * t;
            if (r0 < N_NODES)
                *(float2*)&g_support1[(long)r0 * HIDDEN + c] =
                    make_float2(acc[mi][ni][0], acc[mi][ni][1]);
            if (r1 < N_NODES)
                *(float2*)&g_support1[(long)r1 * HIDDEN + c] =
                    make_float2(acc[mi][ni][2], acc[mi][ni][3]);
        }
    }
}

// ---------------- SpMM1: h1 = relu(gather_sum(support1[src]*val) + b1) ------
__global__ __launch_bounds__(256) void spmm1_kernel(const float* __restrict__ b1) {
    int warp = (blockIdx.x * blockDim.x + threadIdx.x) >> 5;
    int lane = threadIdx.x & 31;
    if (warp >= N_NODES) return;
    int beg = g_row_ptr[warp];
    int end = g_row_ptr[warp + 1];
    float4 acc = make_float4(0.f, 0.f, 0.f, 0.f);
    for (int e = beg; e < end; e++) {
        int2  ed = g_edges[e];
        float v  = __int_as_float(ed.y);
        float4 sup = *(const float4*)&g_support1[(long)ed.x * HIDDEN + lane * 4];
        acc.x += v * sup.x; acc.y += v * sup.y;
        acc.z += v * sup.z; acc.w += v * sup.w;
    }
    float4 bb = *(const float4*)&b1[lane * 4];
    acc.x = fmaxf(acc.x + bb.x, 0.f);
    acc.y = fmaxf(acc.y + bb.y, 0.f);
    acc.z = fmaxf(acc.z + bb.z, 0.f);
    acc.w = fmaxf(acc.w + bb.w, 0.f);
    *(float4*)&g_h1[(long)warp * HIDDEN + lane * 4] = acc;
}

// ---------------- GEMM2: support2 = h1[100000,128] @ W2[128,40] -------------
#define G2_SMEM (128 * 129 * 4 + 128 * 40 * 4)

__global__ __launch_bounds__(256) void gemm2_kernel(const float* __restrict__ W2) {
    extern __shared__ float sh[];
    float* shH = sh;               // [128][129] padded
    float* shW = sh + 128 * 129;   // [128][40]
    int tid = threadIdx.x;
    int row0 = blockIdx.x * 128;

    for (int i = tid; i < 128 * 32; i += 256) {
        int r = i >> 5, c4 = (i & 31) * 4;
        float4 v = make_float4(0.f, 0.f, 0.f, 0.f);
        if (row0 + r < N_NODES)
            v = *(const float4*)&g_h1[(long)(row0 + r) * HIDDEN + c4];
        shH[r * 129 + c4 + 0] = v.x;
        shH[r * 129 + c4 + 1] = v.y;
        shH[r * 129 + c4 + 2] = v.z;
        shH[r * 129 + c4 + 3] = v.w;
    }
    for (int i = tid; i < 128 * 40; i += 256) shW[i] = W2[i];
    __syncthreads();

    int tr = tid >> 3;          // 0..31
    int tc = (tid & 7) * 5;     // 0,5,...,35
    float acc[4][5];
#pragma unroll
    for (int i = 0; i < 4; i++)
#pragma unroll
        for (int j = 0; j < 5; j++) acc[i][j] = 0.f;

    for (int k = 0; k < 128; k++) {
        float a[4], b[5];
#pragma unroll
        for (int i = 0; i < 4; i++) a[i] = shH[(tr + 32 * i) * 129 + k];
#pragma unroll
        for (int j = 0; j < 5; j++) b[j] = shW[k * 40 + tc + j];
#pragma unroll
        for (int i = 0; i < 4; i++)
#pragma unroll
            for (int j = 0; j < 5; j++) acc[i][j] += a[i] * b[j];
    }
#pragma unroll
    for (int i = 0; i < 4; i++) {
        int r = row0 + tr + 32 * i;
        if (r < N_NODES) {
#pragma unroll
            for (int j = 0; j < 5; j++)
                g_support2[(long)r * NCLASS + tc + j] = acc[i][j];
        }
    }
}

// ---------------- SpMM2 + bias + log_softmax --------------------------------
__global__ __launch_bounds__(256) void spmm2_softmax_kernel(const float* __restrict__ b2,
                                                            float* __restrict__ out) {
    int warp = (blockIdx.x * blockDim.x + threadIdx.x) >> 5;
    int lane = threadIdx.x & 31;
    if (warp >= N_NODES) return;
    int beg = g_row_ptr[warp];
    int end = g_row_ptr[warp + 1];
    int  c0 = lane;
    int  c1 = lane + 32;
    bool has1 = (c1 < NCLASS);
    float a0 = 0.f, a1 = 0.f;
    for (int e = beg; e < end; e++) {
        int2  ed = g_edges[e];
        float v  = __int_as_float(ed.y);
        const float* row = &g_support2[(long)ed.x * NCLASS];
        a0 += v * row[c0];
        if (has1) a1 += v * row[c1];
    }
    float z0 = a0 + b2[c0];
    float z1 = has1 ? (a1 + b2[c1]) : -INFINITY;
    float m = fmaxf(z0, z1);
#pragma unroll
    for (int off = 16; off > 0; off >>= 1)
        m = fmaxf(m, __shfl_xor_sync(0xFFFFFFFFu, m, off));
    float s = expf(z0 - m) + (has1 ? expf(z1 - m) : 0.f);
#pragma unroll
    for (int off = 16; off > 0; off >>= 1)
        s += __shfl_xor_sync(0xFFFFFFFFu, s, off);
    float L = m + logf(s);
    out[(long)warp * NCLASS + c0] = z0 - L;
    if (has1) out[(long)warp * NCLASS + c1] = z1 - L;
}

// ---------------- launch -----------------------------------------------------
extern "C" void kernel_launch(void* const* d_in, const int* in_sizes, int n_in,
                              void* d_out, int out_size) {
    const float* x        = (const float*)d_in[0];
    const int*   edge_src = (const int*)d_in[1];
    const int*   edge_dst = (const int*)d_in[2];
    const float* edge_val = (const float*)d_in[3];
    const float* W1       = (const float*)d_in[4];
    const float* b1       = (const float*)d_in[5];
    const float* W2       = (const float*)d_in[6];
    const float* b2       = (const float*)d_in[7];
    float* out = (float*)d_out;

    (void)in_sizes; (void)n_in; (void)out_size;

    cudaFuncSetAttribute(gemm1_tf32_kernel, cudaFuncAttributeMaxDynamicSharedMemorySize, G1_SMEM);
    cudaFuncSetAttribute(gemm2_kernel, cudaFuncAttributeMaxDynamicSharedMemorySize, G2_SMEM);

    // CSR build
    zero_deg_kernel<<<(N_NODES + 255) / 256, 256>>>();
    hist_kernel<<<(N_EDGES + 255) / 256, 256>>>(edge_dst);
    scan_phase1<<<N_SBLOCKS, 256>>>();
    scan_phase2<<<1, 128>>>();
    scan_phase3<<<N_SBLOCKS, 256>>>();
    scatter_kernel<<<(N_EDGES + 255) / 256, 256>>>(edge_src, edge_dst, edge_val);

    // layer 1
    gemm1_tf32_kernel<<<(N_NODES + G1_BM - 1) / G1_BM, 256, G1_SMEM>>>(x, W1);
    spmm1_kernel<<<(N_NODES * 32 + 255) / 256, 256>>>(b1);

    // layer 2
    gemm2_kernel<<<(N_NODES + 127) / 128, 256, G2_SMEM>>>(W2);
    spmm2_softmax_kernel<<<(N_NODES * 32 + 255) / 256, 256>>>(b2, out);
}

// round 4
// speedup vs baseline: 2.2330x; 1.0322x over previous
#include <cuda_runtime.h>
#include <math.h>
#include <stdint.h>

#define N_NODES 100000
#define N_EDGES 1600000
#define NFEAT   512
#define HIDDEN  128
#define NCLASS  40

// ---------------- scratch (device globals; no allocation allowed) ----------
__device__ float g_support1[(long)N_NODES * HIDDEN];   // X @ W1
__device__ float g_h1[(long)N_NODES * HIDDEN];         // relu(agg + b1)
__device__ float g_support2[(long)N_NODES * NCLASS];   // h1 @ W2
__device__ int   g_deg[N_NODES];
__device__ int   g_row_ptr[N_NODES + 1];
__device__ int   g_cursor[N_NODES];
__device__ int2  g_edges[N_EDGES];                     // {src, val bits}
__device__ int   g_psum[128];                          // block partial sums

#define SCAN_TILE 1024
#define N_SBLOCKS ((N_NODES + SCAN_TILE - 1) / SCAN_TILE)   // 98

// ---------------- CSR build --------------------------------------------------
__global__ void zero_deg_kernel() {
    int i = blockIdx.x * blockDim.x + threadIdx.x;
    if (i < N_NODES) g_deg[i] = 0;
}

__global__ void hist_kernel(const int* __restrict__ dst) {
    int i = blockIdx.x * blockDim.x + threadIdx.x;
    if (i < N_EDGES) atomicAdd(&g_deg[dst[i]], 1);
}

// phase 1: per-block (1024 elems) totals
__global__ __launch_bounds__(256) void scan_phase1() {
    int b = blockIdx.x, tid = threadIdx.x;
    int lane = tid & 31, warp = tid >> 5;
    int base = b * SCAN_TILE + tid * 4;
    int s = 0;
#pragma unroll
    for (int j = 0; j < 4; j++) {
        int i = base + j;
        if (i < N_NODES) s += g_deg[i];
    }
#pragma unroll
    for (int off = 16; off > 0; off >>= 1)
        s += __shfl_xor_sync(0xFFFFFFFFu, s, off);
    __shared__ int wsum[8];
    if (lane == 0) wsum[warp] = s;
    __syncthreads();
    if (tid == 0) {
        int t = 0;
#pragma unroll
        for (int w = 0; w < 8; w++) t += wsum[w];
        g_psum[b] = t;
    }
}

// phase 2: exclusive scan of 98 block totals (single block)
__global__ __launch_bounds__(128) void scan_phase2() {
    int tid = threadIdx.x;
    __shared__ int sh[128];
    int v = (tid < N_SBLOCKS) ? g_psum[tid] : 0;
    sh[tid] = v;
    __syncthreads();
#pragma unroll
    for (int off = 1; off < 128; off <<= 1) {
        int t = (tid >= off) ? sh[tid - off] : 0;
        __syncthreads();
        sh[tid] += t;
        __syncthreads();
    }
    if (tid < N_SBLOCKS) g_psum[tid] = sh[tid] - v;   // exclusive
}

// phase 3: local scan + block offset -> row_ptr, cursor
__global__ __launch_bounds__(256) void scan_phase3() {
    int b = blockIdx.x, tid = threadIdx.x;
    int lane = tid & 31, warp = tid >> 5;
    int base = b * SCAN_TILE + tid * 4;
    int v[4], tsum = 0;
#pragma unroll
    for (int j = 0; j < 4; j++) {
        int i = base + j;
        v[j] = (i < N_NODES) ? g_deg[i] : 0;
        tsum += v[j];
    }
    int incl = tsum;
#pragma unroll
    for (int off = 1; off < 32; off <<= 1) {
        int n = __shfl_up_sync(0xFFFFFFFFu, incl, off);
        if (lane >= off) incl += n;
    }
    __shared__ int wtot[8];
    if (lane == 31) wtot[warp] = incl;
    __syncthreads();
    if (warp == 0 && lane < 8) {
        int wv = wtot[lane];
        int wincl = wv;
#pragma unroll
        for (int off = 1; off < 8; off <<= 1) {
            int n = __shfl_up_sync(0xFFu, wincl, off);
            if (lane >= off) wincl += n;
        }
        wtot[lane] = wincl - wv;   // exclusive among warps
    }
    __syncthreads();
    int run = g_psum[b] + wtot[warp] + incl - tsum;
#pragma unroll
    for (int j = 0; j < 4; j++) {
        int i = base + j;
        if (i < N_NODES) { g_row_ptr[i] = run; g_cursor[i] = run; }
        run += v[j];
    }
    if (b == 0 && tid == 0) g_row_ptr[N_NODES] = N_EDGES;
}

__global__ void scatter_kernel(const int* __restrict__ src,
                               const int* __restrict__ dst,
                               const float* __restrict__ val) {
    int i = blockIdx.x * blockDim.x + threadIdx.x;
    if (i < N_EDGES) {
        int d = dst[i];
        int p = atomicAdd(&g_cursor[d], 1);
        g_edges[p] = make_int2(src[i], __float_as_int(val[i]));
    }
}

// ---------------- GEMM1 (tf32 tensor cores, cp.async double-buffered) -------
// support1 = X[100000,512] @ W1[512,128]
#define G1_BM 128
#define G1_BK 32
#define AS_STRIDE 36    // words; 144B rows -> 16B aligned chunks
#define BS_STRIDE 132   // words; 528B rows -> 16B aligned chunks
#define AS_WORDS (G1_BM * AS_STRIDE)   // 4608
#define BS_WORDS (G1_BK * BS_STRIDE)   // 4224
#define G1_SMEM ((2 * AS_WORDS + 2 * BS_WORDS) * 4)

__device__ __forceinline__ void cp16(uint32_t dst, const void* src, bool pred) {
    int sz = pred ? 16 : 0;
    asm volatile("cp.async.cg.shared.global [%0], [%1], 16, %2;\n"
                 :: "r"(dst), "l"(src), "r"(sz));
}

__global__ __launch_bounds__(256, 2) void gemm1_tf32_kernel(const float* __restrict__ A,
                                                            const float* __restrict__ B) {
    extern __shared__ uint32_t g1sh[];
    uint32_t* As = g1sh;                 // [2][AS_WORDS]
    uint32_t* Bs = g1sh + 2 * AS_WORDS;  // [2][BS_WORDS]
    const uint32_t smem_base = (uint32_t)__cvta_generic_to_shared(g1sh);

    const int tid  = threadIdx.x;
    const int warp = tid >> 5;
    const int lane = tid & 31;
    const int g = lane >> 2;           // 0..7
    const int t = lane & 3;            // 0..3
    const int wm = (warp >> 2) * 64;   // 0 or 64
    const int wn = (warp & 3) * 32;    // 0,32,64,96
    const int block_row = blockIdx.x * G1_BM;

    float acc[4][4][4];
#pragma unroll
    for (int mi = 0; mi < 4; mi++)
#pragma unroll
        for (int ni = 0; ni < 4; ni++)
#pragma unroll
            for (int q = 0; q < 4; q++) acc[mi][ni][q] = 0.f;

    // tile loader: A 128x32 (1024 16B-chunks), B 32x128 (1024 16B-chunks)
    auto load_tile = [&](int buf, int k0) {
#pragma unroll
        for (int j = 0; j < 4; j++) {
            int chunk = tid + j * 256;
            int row = chunk >> 3;
            int col = (chunk & 7) * 4;
            int gr = block_row + row;
            bool ok = gr < N_NODES;
            const float* src = A + (long)(ok ? gr : 0) * NFEAT + k0 + col;
            uint32_t dst = smem_base + (buf * AS_WORDS + row * AS_STRIDE + col) * 4;
            cp16(dst, src, ok);
        }
#pragma unroll
        for (int j = 0; j < 4; j++) {
            int chunk = tid + j * 256;
            int row = chunk >> 5;
            int col = (chunk & 31) * 4;
            const float* src = B + (long)(k0 + row) * HIDDEN + col;
            uint32_t dst = smem_base + (2 * AS_WORDS + buf * BS_WORDS + row * BS_STRIDE + col) * 4;
            cp16(dst, src, true);
        }
    };

    const int NT = NFEAT / G1_BK;   // 16
    load_tile(0, 0);
    asm volatile("cp.async.commit_group;\n");

    for (int kt = 0; kt < NT; kt++) {
        int buf = kt & 1;
        if (kt + 1 < NT) {
            load_tile(buf ^ 1, (kt + 1) * G1_BK);
            asm volatile("cp.async.commit_group;\n");
            asm volatile("cp.async.wait_group 1;\n");
        } else {
            asm volatile("cp.async.wait_group 0;\n");
        }
        __syncthreads();

        const uint32_t* Ab = As + buf * AS_WORDS;
        const uint32_t* Bb = Bs + buf * BS_WORDS;
#pragma unroll
        for (int kk = 0; kk < 4; kk++) {
            const int kb = kk * 8;
            uint32_t af[4][4], bf[4][2];
#pragma unroll
            for (int mi = 0; mi < 4; mi++) {
                int r0 = wm + mi * 16 + g;
                af[mi][0] = Ab[(r0)     * AS_STRIDE + kb + t];
                af[mi][1] = Ab[(r0 + 8) * AS_STRIDE + kb + t];
                af[mi][2] = Ab[(r0)     * AS_STRIDE + kb + t + 4];
                af[mi][3] = Ab[(r0 + 8) * AS_STRIDE + kb + t + 4];
            }
#pragma unroll
            for (int ni = 0; ni < 4; ni++) {
                int c = wn + ni * 8 + g;
                bf[ni][0] = Bb[(kb + t)     * BS_STRIDE + c];
                bf[ni][1] = Bb[(kb + t + 4) * BS_STRIDE + c];
            }
#pragma unroll
            for (int mi = 0; mi < 4; mi++) {
#pragma unroll
                for (int ni = 0; ni < 4; ni++) {
                    asm volatile(
                        "mma.sync.aligned.m16n8k8.row.col.f32.tf32.tf32.f32 "
                        "{%0,%1,%2,%3}, {%4,%5,%6,%7}, {%8,%9}, {%0,%1,%2,%3};"
                        : "+f"(acc[mi][ni][0]), "+f"(acc[mi][ni][1]),
                          "+f"(acc[mi][ni][2]), "+f"(acc[mi][ni][3])
                        : "r"(af[mi][0]), "r"(af[mi][1]), "r"(af[mi][2]), "r"(af[mi][3]),
                          "r"(bf[ni][0]), "r"(bf[ni][1]));
                }
            }
        }
        __syncthreads();
    }

#pragma unroll
    for (int mi = 0; mi < 4; mi++) {
        int r0 = block_row + wm + mi * 16 + g;
        int r1 = r0 + 8;
#pragma unroll
        for (int ni = 0; ni < 4; ni++) {
            int c = wn + ni * 8 + 2 * t;
            if (r0 < N_NODES)
                *(float2*)&g_support1[(long)r0 * HIDDEN + c] =
                    make_float2(acc[mi][ni][0], acc[mi][ni][1]);
            if (r1 < N_NODES)
                *(float2*)&g_support1[(long)r1 * HIDDEN + c] =
                    make_float2(acc[mi][ni][2], acc[mi][ni][3]);
        }
    }
}

// ---------------- SpMM1: h1 = relu(gather_sum(support1[src]*val) + b1) ------
__global__ __launch_bounds__(256) void spmm1_kernel(const float* __restrict__ b1) {
    int warp = (blockIdx.x * blockDim.x + threadIdx.x) >> 5;
    int lane = threadIdx.x & 31;
    if (warp >= N_NODES) return;
    int beg = g_row_ptr[warp];
    int end = g_row_ptr[warp + 1];
    float4 acc = make_float4(0.f, 0.f, 0.f, 0.f);
    for (int e = beg; e < end; e++) {
        int2  ed = __ldcs(&g_edges[e]);          // streaming, evict-first
        float v  = __int_as_float(ed.y);
        float4 sup = *(const float4*)&g_support1[(long)ed.x * HIDDEN + lane * 4];
        acc.x += v * sup.x; acc.y += v * sup.y;
        acc.z += v * sup.z; acc.w += v * sup.w;
    }
    float4 bb = *(const float4*)&b1[lane * 4];
    acc.x = fmaxf(acc.x + bb.x, 0.f);
    acc.y = fmaxf(acc.y + bb.y, 0.f);
    acc.z = fmaxf(acc.z + bb.z, 0.f);
    acc.w = fmaxf(acc.w + bb.w, 0.f);
    *(float4*)&g_h1[(long)warp * HIDDEN + lane * 4] = acc;
}

// ---------------- GEMM2: support2 = h1[100000,128] @ W2[128,40] -------------
#define G2_SMEM (128 * 129 * 4 + 128 * 40 * 4)

__global__ __launch_bounds__(256) void gemm2_kernel(const float* __restrict__ W2) {
    extern __shared__ float sh[];
    float* shH = sh;               // [128][129] padded
    float* shW = sh + 128 * 129;   // [128][40]
    int tid = threadIdx.x;
    int row0 = blockIdx.x * 128;

    for (int i = tid; i < 128 * 32; i += 256) {
        int r = i >> 5, c4 = (i & 31) * 4;
        float4 v = make_float4(0.f, 0.f, 0.f, 0.f);
        if (row0 + r < N_NODES)
            v = *(const float4*)&g_h1[(long)(row0 + r) * HIDDEN + c4];
        shH[r * 129 + c4 + 0] = v.x;
        shH[r * 129 + c4 + 1] = v.y;
        shH[r * 129 + c4 + 2] = v.z;
        shH[r * 129 + c4 + 3] = v.w;
    }
    for (int i = tid; i < 128 * 40; i += 256) shW[i] = W2[i];
    __syncthreads();

    int tr = tid >> 3;          // 0..31
    int tc = (tid & 7) * 5;     // 0,5,...,35
    float acc[4][5];
#pragma unroll
    for (int i = 0; i < 4; i++)
#pragma unroll
        for (int j = 0; j < 5; j++) acc[i][j] = 0.f;

    for (int k = 0; k < 128; k++) {
        float a[4], b[5];
#pragma unroll
        for (int i = 0; i < 4; i++) a[i] = shH[(tr + 32 * i) * 129 + k];
#pragma unroll
        for (int j = 0; j < 5; j++) b[j] = shW[k * 40 + tc + j];
#pragma unroll
        for (int i = 0; i < 4; i++)
#pragma unroll
            for (int j = 0; j < 5; j++) acc[i][j] += a[i] * b[j];
    }
#pragma unroll
    for (int i = 0; i < 4; i++) {
        int r = row0 + tr + 32 * i;
        if (r < N_NODES) {
#pragma unroll
            for (int j = 0; j < 5; j++)
                g_support2[(long)r * NCLASS + tc + j] = acc[i][j];
        }
    }
}

// ---------------- SpMM2 + bias + log_softmax --------------------------------
__global__ __launch_bounds__(256) void spmm2_softmax_kernel(const float* __restrict__ b2,
                                                            float* __restrict__ out) {
    int warp = (blockIdx.x * blockDim.x + threadIdx.x) >> 5;
    int lane = threadIdx.x & 31;
    if (warp >= N_NODES) return;
    int beg = g_row_ptr[warp];
    int end = g_row_ptr[warp + 1];
    int  c0 = lane;
    int  c1 = lane + 32;
    bool has1 = (c1 < NCLASS);
    float a0 = 0.f, a1 = 0.f;
    for (int e = beg; e < end; e++) {
        int2  ed = __ldcs(&g_edges[e]);          // streaming, evict-first
        float v  = __int_as_float(ed.y);
        const float* row = &g_support2[(long)ed.x * NCLASS];
        a0 += v * row[c0];
        if (has1) a1 += v * row[c1];
    }
    float z0 = a0 + b2[c0];
    float z1 = has1 ? (a1 + b2[c1]) : -INFINITY;
    float m = fmaxf(z0, z1);
#pragma unroll
    for (int off = 16; off > 0; off >>= 1)
        m = fmaxf(m, __shfl_xor_sync(0xFFFFFFFFu, m, off));
    float s = expf(z0 - m) + (has1 ? expf(z1 - m) : 0.f);
#pragma unroll
    for (int off = 16; off > 0; off >>= 1)
        s += __shfl_xor_sync(0xFFFFFFFFu, s, off);
    float L = m + logf(s);
    out[(long)warp * NCLASS + c0] = z0 - L;
    if (has1) out[(long)warp * NCLASS + c1] = z1 - L;
}

// ---------------- launch -----------------------------------------------------
extern "C" void kernel_launch(void* const* d_in, const int* in_sizes, int n_in,
                              void* d_out, int out_size) {
    const float* x        = (const float*)d_in[0];
    const int*   edge_src = (const int*)d_in[1];
    const int*   edge_dst = (const int*)d_in[2];
    const float* edge_val = (const float*)d_in[3];
    const float* W1       = (const float*)d_in[4];
    const float* b1       = (const float*)d_in[5];
    const float* W2       = (const float*)d_in[6];
    const float* b2       = (const float*)d_in[7];
    float* out = (float*)d_out;

    (void)in_sizes; (void)n_in; (void)out_size;

    // one-time host-side resources (no device memory involved)
    static cudaStream_t s_csr = nullptr;
    static cudaEvent_t  ev_fork = nullptr, ev_join = nullptr;
    static bool s_init = false;
    if (!s_init) {
        cudaStreamCreateWithFlags(&s_csr, cudaStreamNonBlocking);
        cudaEventCreateWithFlags(&ev_fork, cudaEventDisableTiming);
        cudaEventCreateWithFlags(&ev_join, cudaEventDisableTiming);
        cudaFuncSetAttribute(gemm1_tf32_kernel, cudaFuncAttributeMaxDynamicSharedMemorySize, G1_SMEM);
        cudaFuncSetAttribute(gemm2_kernel, cudaFuncAttributeMaxDynamicSharedMemorySize, G2_SMEM);
        s_init = true;
    }

    // fork: CSR build on side stream, gemm1 on main (capture) stream
    cudaEventRecord(ev_fork, 0);
    cudaStreamWaitEvent(s_csr, ev_fork, 0);

    zero_deg_kernel<<<(N_NODES + 255) / 256, 256, 0, s_csr>>>();
    hist_kernel<<<(N_EDGES + 255) / 256, 256, 0, s_csr>>>(edge_dst);
    scan_phase1<<<N_SBLOCKS, 256, 0, s_csr>>>();
    scan_phase2<<<1, 128, 0, s_csr>>>();
    scan_phase3<<<N_SBLOCKS, 256, 0, s_csr>>>();
    scatter_kernel<<<(N_EDGES + 255) / 256, 256, 0, s_csr>>>(edge_src, edge_dst, edge_val);
    cudaEventRecord(ev_join, s_csr);

    // main stream: dense transform (independent of CSR)
    gemm1_tf32_kernel<<<(N_NODES + G1_BM - 1) / G1_BM, 256, G1_SMEM>>>(x, W1);

    // join: spmm1 needs both CSR and support1
    cudaStreamWaitEvent(0, ev_join, 0);

    spmm1_kernel<<<(N_NODES * 32 + 255) / 256, 256>>>(b1);
    gemm2_kernel<<<(N_NODES + 127) / 128, 256, G2_SMEM>>>(W2);
    spmm2_softmax_kernel<<<(N_NODES * 32 + 255) / 256, 256>>>(b2, out);
}

// round 5
// speedup vs baseline: 2.3452x; 1.0502x over previous
#include <cuda_runtime.h>
#include <cuda_fp16.h>
#include <math.h>
#include <stdint.h>

#define N_NODES 100000
#define N_EDGES 1600000
#define NFEAT   512
#define HIDDEN  128
#define NCLASS  40

// ---------------- scratch (device globals; no allocation allowed) ----------
__device__ __half g_support1h[(long)N_NODES * HIDDEN]; // X @ W1 (fp16 storage)
__device__ float  g_h1[(long)N_NODES * HIDDEN];        // relu(agg + b1)
__device__ float  g_support2[(long)N_NODES * NCLASS];  // h1 @ W2
__device__ int    g_deg[N_NODES];
__device__ int    g_row_ptr[N_NODES + 1];
__device__ int    g_cursor[N_NODES];
__device__ int2   g_edges[N_EDGES];                    // {src, val bits}
__device__ int    g_psum[128];                         // block partial sums

#define SCAN_TILE 1024
#define N_SBLOCKS ((N_NODES + SCAN_TILE - 1) / SCAN_TILE)   // 98

// ---------------- CSR build --------------------------------------------------
__global__ void zero_deg_kernel() {
    int i = blockIdx.x * blockDim.x + threadIdx.x;
    if (i < N_NODES) g_deg[i] = 0;
}

__global__ void hist_kernel(const int* __restrict__ dst) {
    int i = blockIdx.x * blockDim.x + threadIdx.x;
    if (i < N_EDGES) atomicAdd(&g_deg[dst[i]], 1);
}

__global__ __launch_bounds__(256) void scan_phase1() {
    int b = blockIdx.x, tid = threadIdx.x;
    int lane = tid & 31, warp = tid >> 5;
    int base = b * SCAN_TILE + tid * 4;
    int s = 0;
#pragma unroll
    for (int j = 0; j < 4; j++) {
        int i = base + j;
        if (i < N_NODES) s += g_deg[i];
    }
#pragma unroll
    for (int off = 16; off > 0; off >>= 1)
        s += __shfl_xor_sync(0xFFFFFFFFu, s, off);
    __shared__ int wsum[8];
    if (lane == 0) wsum[warp] = s;
    __syncthreads();
    if (tid == 0) {
        int t = 0;
#pragma unroll
        for (int w = 0; w < 8; w++) t += wsum[w];
        g_psum[b] = t;
    }
}

__global__ __launch_bounds__(128) void scan_phase2() {
    int tid = threadIdx.x;
    __shared__ int sh[128];
    int v = (tid < N_SBLOCKS) ? g_psum[tid] : 0;
    sh[tid] = v;
    __syncthreads();
#pragma unroll
    for (int off = 1; off < 128; off <<= 1) {
        int t = (tid >= off) ? sh[tid - off] : 0;
        __syncthreads();
        sh[tid] += t;
        __syncthreads();
    }
    if (tid < N_SBLOCKS) g_psum[tid] = sh[tid] - v;   // exclusive
}

__global__ __launch_bounds__(256) void scan_phase3() {
    int b = blockIdx.x, tid = threadIdx.x;
    int lane = tid & 31, warp = tid >> 5;
    int base = b * SCAN_TILE + tid * 4;
    int v[4], tsum = 0;
#pragma unroll
    for (int j = 0; j < 4; j++) {
        int i = base + j;
        v[j] = (i < N_NODES) ? g_deg[i] : 0;
        tsum += v[j];
    }
    int incl = tsum;
#pragma unroll
    for (int off = 1; off < 32; off <<= 1) {
        int n = __shfl_up_sync(0xFFFFFFFFu, incl, off);
        if (lane >= off) incl += n;
    }
    __shared__ int wtot[8];
    if (lane == 31) wtot[warp] = incl;
    __syncthreads();
    if (warp == 0 && lane < 8) {
        int wv = wtot[lane];
        int wincl = wv;
#pragma unroll
        for (int off = 1; off < 8; off <<= 1) {
            int n = __shfl_up_sync(0xFFu, wincl, off);
            if (lane >= off) wincl += n;
        }
        wtot[lane] = wincl - wv;
    }
    __syncthreads();
    int run = g_psum[b] + wtot[warp] + incl - tsum;
#pragma unroll
    for (int j = 0; j < 4; j++) {
        int i = base + j;
        if (i < N_NODES) { g_row_ptr[i] = run; g_cursor[i] = run; }
        run += v[j];
    }
    if (b == 0 && tid == 0) g_row_ptr[N_NODES] = N_EDGES;
}

__global__ void scatter_kernel(const int* __restrict__ src,
                               const int* __restrict__ dst,
                               const float* __restrict__ val) {
    int i = blockIdx.x * blockDim.x + threadIdx.x;
    if (i < N_EDGES) {
        int d = dst[i];
        int p = atomicAdd(&g_cursor[d], 1);
        g_edges[p] = make_int2(src[i], __float_as_int(val[i]));
    }
}

// ---------------- GEMM1 (tf32 tensor cores, cp.async double-buffered) -------
// support1 = X[100000,512] @ W1[512,128], output stored fp16
#define G1_BM 128
#define G1_BK 32
#define AS_STRIDE 36
#define BS_STRIDE 132
#define AS_WORDS (G1_BM * AS_STRIDE)
#define BS_WORDS (G1_BK * BS_STRIDE)
#define G1_SMEM ((2 * AS_WORDS + 2 * BS_WORDS) * 4)

__device__ __forceinline__ void cp16(uint32_t dst, const void* src, bool pred) {
    int sz = pred ? 16 : 0;
    asm volatile("cp.async.cg.shared.global [%0], [%1], 16, %2;\n"
                 :: "r"(dst), "l"(src), "r"(sz));
}

__device__ __forceinline__ uint32_t rna_tf32(uint32_t raw) {
    uint32_t u;
    asm("cvt.rna.tf32.f32 %0, %1;" : "=r"(u) : "f"(__int_as_float(raw)));
    return u;
}

__global__ __launch_bounds__(256, 2) void gemm1_tf32_kernel(const float* __restrict__ A,
                                                            const float* __restrict__ B) {
    extern __shared__ uint32_t g1sh[];
    uint32_t* As = g1sh;                 // [2][AS_WORDS]
    uint32_t* Bs = g1sh + 2 * AS_WORDS;  // [2][BS_WORDS]
    const uint32_t smem_base = (uint32_t)__cvta_generic_to_shared(g1sh);

    const int tid  = threadIdx.x;
    const int warp = tid >> 5;
    const int lane = tid & 31;
    const int g = lane >> 2;
    const int t = lane & 3;
    const int wm = (warp >> 2) * 64;
    const int wn = (warp & 3) * 32;
    const int block_row = blockIdx.x * G1_BM;

    float acc[4][4][4];
#pragma unroll
    for (int mi = 0; mi < 4; mi++)
#pragma unroll
        for (int ni = 0; ni < 4; ni++)
#pragma unroll
            for (int q = 0; q < 4; q++) acc[mi][ni][q] = 0.f;

    auto load_tile = [&](int buf, int k0) {
#pragma unroll
        for (int j = 0; j < 4; j++) {
            int chunk = tid + j * 256;
            int row = chunk >> 3;
            int col = (chunk & 7) * 4;
            int gr = block_row + row;
            bool ok = gr < N_NODES;
            const float* src = A + (long)(ok ? gr : 0) * NFEAT + k0 + col;
            uint32_t dst = smem_base + (buf * AS_WORDS + row * AS_STRIDE + col) * 4;
            cp16(dst, src, ok);
        }
#pragma unroll
        for (int j = 0; j < 4; j++) {
            int chunk = tid + j * 256;
            int row = chunk >> 5;
            int col = (chunk & 31) * 4;
            const float* src = B + (long)(k0 + row) * HIDDEN + col;
            uint32_t dst = smem_base + (2 * AS_WORDS + buf * BS_WORDS + row * BS_STRIDE + col) * 4;
            cp16(dst, src, true);
        }
    };

    const int NT = NFEAT / G1_BK;   // 16
    load_tile(0, 0);
    asm volatile("cp.async.commit_group;\n");

    for (int kt = 0; kt < NT; kt++) {
        int buf = kt & 1;
        if (kt + 1 < NT) {
            load_tile(buf ^ 1, (kt + 1) * G1_BK);
            asm volatile("cp.async.commit_group;\n");
            asm volatile("cp.async.wait_group 1;\n");
        } else {
            asm volatile("cp.async.wait_group 0;\n");
        }
        __syncthreads();

        const uint32_t* Ab = As + buf * AS_WORDS;
        const uint32_t* Bb = Bs + buf * BS_WORDS;
#pragma unroll
        for (int kk = 0; kk < 4; kk++) {
            const int kb = kk * 8;
            uint32_t af[4][4], bf[4][2];
#pragma unroll
            for (int mi = 0; mi < 4; mi++) {
                int r0 = wm + mi * 16 + g;
                af[mi][0] = rna_tf32(Ab[(r0)     * AS_STRIDE + kb + t]);
                af[mi][1] = rna_tf32(Ab[(r0 + 8) * AS_STRIDE + kb + t]);
                af[mi][2] = rna_tf32(Ab[(r0)     * AS_STRIDE + kb + t + 4]);
                af[mi][3] = rna_tf32(Ab[(r0 + 8) * AS_STRIDE + kb + t + 4]);
            }
#pragma unroll
            for (int ni = 0; ni < 4; ni++) {
                int c = wn + ni * 8 + g;
                bf[ni][0] = rna_tf32(Bb[(kb + t)     * BS_STRIDE + c]);
                bf[ni][1] = rna_tf32(Bb[(kb + t + 4) * BS_STRIDE + c]);
            }
#pragma unroll
            for (int mi = 0; mi < 4; mi++) {
#pragma unroll
                for (int ni = 0; ni < 4; ni++) {
                    asm volatile(
                        "mma.sync.aligned.m16n8k8.row.col.f32.tf32.tf32.f32 "
                        "{%0,%1,%2,%3}, {%4,%5,%6,%7}, {%8,%9}, {%0,%1,%2,%3};"
                        : "+f"(acc[mi][ni][0]), "+f"(acc[mi][ni][1]),
                          "+f"(acc[mi][ni][2]), "+f"(acc[mi][ni][3])
                        : "r"(af[mi][0]), "r"(af[mi][1]), "r"(af[mi][2]), "r"(af[mi][3]),
                          "r"(bf[ni][0]), "r"(bf[ni][1]));
                }
            }
        }
        __syncthreads();
    }

    // epilogue: fp16 store (half2 per (c, c+1) pair)
#pragma unroll
    for (int mi = 0; mi < 4; mi++) {
        int r0 = block_row + wm + mi * 16 + g;
        int r1 = r0 + 8;
#pragma unroll
        for (int ni = 0; ni < 4; ni++) {
            int c = wn + ni * 8 + 2 * t;
            if (r0 < N_NODES)
                *(__half2*)&g_support1h[(long)r0 * HIDDEN + c] =
                    __floats2half2_rn(acc[mi][ni][0], acc[mi][ni][1]);
            if (r1 < N_NODES)
                *(__half2*)&g_support1h[(long)r1 * HIDDEN + c] =
                    __floats2half2_rn(acc[mi][ni][2], acc[mi][ni][3]);
        }
    }
}

// ---------------- SpMM1: h1 = relu(gather_sum(support1h[src]*val) + b1) -----
__global__ __launch_bounds__(256) void spmm1_kernel(const float* __restrict__ b1) {
    int warp = (blockIdx.x * blockDim.x + threadIdx.x) >> 5;
    int lane = threadIdx.x & 31;
    if (warp >= N_NODES) return;
    int beg = g_row_ptr[warp];
    int end = g_row_ptr[warp + 1];
    float4 acc = make_float4(0.f, 0.f, 0.f, 0.f);
    for (int e = beg; e < end; e++) {
        int2  ed = __ldcs(&g_edges[e]);
        float v  = __int_as_float(ed.y);
        // 4 features per lane = 2 half2 = one 8B load
        uint2 u = *(const uint2*)&g_support1h[(long)ed.x * HIDDEN + lane * 4];
        float2 f0 = __half22float2(*(__half2*)&u.x);
        float2 f1 = __half22float2(*(__half2*)&u.y);
        acc.x += v * f0.x; acc.y += v * f0.y;
        acc.z += v * f1.x; acc.w += v * f1.y;
    }
    float4 bb = *(const float4*)&b1[lane * 4];
    acc.x = fmaxf(acc.x + bb.x, 0.f);
    acc.y = fmaxf(acc.y + bb.y, 0.f);
    acc.z = fmaxf(acc.z + bb.z, 0.f);
    acc.w = fmaxf(acc.w + bb.w, 0.f);
    *(float4*)&g_h1[(long)warp * HIDDEN + lane * 4] = acc;
}

// ---------------- GEMM2: support2 = h1[100000,128] @ W2[128,40] -------------
#define G2_SMEM (128 * 129 * 4 + 128 * 40 * 4)

__global__ __launch_bounds__(256) void gemm2_kernel(const float* __restrict__ W2) {
    extern __shared__ float sh[];
    float* shH = sh;
    float* shW = sh + 128 * 129;
    int tid = threadIdx.x;
    int row0 = blockIdx.x * 128;

    for (int i = tid; i < 128 * 32; i += 256) {
        int r = i >> 5, c4 = (i & 31) * 4;
        float4 v = make_float4(0.f, 0.f, 0.f, 0.f);
        if (row0 + r < N_NODES)
            v = *(const float4*)&g_h1[(long)(row0 + r) * HIDDEN + c4];
        shH[r * 129 + c4 + 0] = v.x;
        shH[r * 129 + c4 + 1] = v.y;
        shH[r * 129 + c4 + 2] = v.z;
        shH[r * 129 + c4 + 3] = v.w;
    }
    for (int i = tid; i < 128 * 40; i += 256) shW[i] = W2[i];
    __syncthreads();

    int tr = tid >> 3;
    int tc = (tid & 7) * 5;
    float acc[4][5];
#pragma unroll
    for (int i = 0; i < 4; i++)
#pragma unroll
        for (int j = 0; j < 5; j++) acc[i][j] = 0.f;

    for (int k = 0; k < 128; k++) {
        float a[4], b[5];
#pragma unroll
        for (int i = 0; i < 4; i++) a[i] = shH[(tr + 32 * i) * 129 + k];
#pragma unroll
        for (int j = 0; j < 5; j++) b[j] = shW[k * 40 + tc + j];
#pragma unroll
        for (int i = 0; i < 4; i++)
#pragma unroll
            for (int j = 0; j < 5; j++) acc[i][j] += a[i] * b[j];
    }
#pragma unroll
    for (int i = 0; i < 4; i++) {
        int r = row0 + tr + 32 * i;
        if (r < N_NODES) {
#pragma unroll
            for (int j = 0; j < 5; j++)
                g_support2[(long)r * NCLASS + tc + j] = acc[i][j];
        }
    }
}

// ---------------- SpMM2 + bias + log_softmax --------------------------------
__global__ __launch_bounds__(256) void spmm2_softmax_kernel(const float* __restrict__ b2,
                                                            float* __restrict__ out) {
    int warp = (blockIdx.x * blockDim.x + threadIdx.x) >> 5;
    int lane = threadIdx.x & 31;
    if (warp >= N_NODES) return;
    int beg = g_row_ptr[warp];
    int end = g_row_ptr[warp + 1];
    int  c0 = lane;
    int  c1 = lane + 32;
    bool has1 = (c1 < NCLASS);
    float a0 = 0.f, a1 = 0.f;
    for (int e = beg; e < end; e++) {
        int2  ed = __ldcs(&g_edges[e]);
        float v  = __int_as_float(ed.y);
        const float* row = &g_support2[(long)ed.x * NCLASS];
        a0 += v * row[c0];
        if (has1) a1 += v * row[c1];
    }
    float z0 = a0 + b2[c0];
    float z1 = has1 ? (a1 + b2[c1]) : -INFINITY;
    float m = fmaxf(z0, z1);
#pragma unroll
    for (int off = 16; off > 0; off >>= 1)
        m = fmaxf(m, __shfl_xor_sync(0xFFFFFFFFu, m, off));
    float s = expf(z0 - m) + (has1 ? expf(z1 - m) : 0.f);
#pragma unroll
    for (int off = 16; off > 0; off >>= 1)
        s += __shfl_xor_sync(0xFFFFFFFFu, s, off);
    float L = m + logf(s);
    out[(long)warp * NCLASS + c0] = z0 - L;
    if (has1) out[(long)warp * NCLASS + c1] = z1 - L;
}

// ---------------- launch -----------------------------------------------------
extern "C" void kernel_launch(void* const* d_in, const int* in_sizes, int n_in,
                              void* d_out, int out_size) {
    const float* x        = (const float*)d_in[0];
    const int*   edge_src = (const int*)d_in[1];
    const int*   edge_dst = (const int*)d_in[2];
    const float* edge_val = (const float*)d_in[3];
    const float* W1       = (const float*)d_in[4];
    const float* b1       = (const float*)d_in[5];
    const float* W2       = (const float*)d_in[6];
    const float* b2       = (const float*)d_in[7];
    float* out = (float*)d_out;

    (void)in_sizes; (void)n_in; (void)out_size;

    static cudaStream_t s_csr = nullptr;
    static cudaEvent_t  ev_fork = nullptr, ev_join = nullptr;
    static bool s_init = false;
    if (!s_init) {
        cudaStreamCreateWithFlags(&s_csr, cudaStreamNonBlocking);
        cudaEventCreateWithFlags(&ev_fork, cudaEventDisableTiming);
        cudaEventCreateWithFlags(&ev_join, cudaEventDisableTiming);
        cudaFuncSetAttribute(gemm1_tf32_kernel, cudaFuncAttributeMaxDynamicSharedMemorySize, G1_SMEM);
        cudaFuncSetAttribute(gemm2_kernel, cudaFuncAttributeMaxDynamicSharedMemorySize, G2_SMEM);
        s_init = true;
    }

    cudaEventRecord(ev_fork, 0);
    cudaStreamWaitEvent(s_csr, ev_fork, 0);

    zero_deg_kernel<<<(N_NODES + 255) / 256, 256, 0, s_csr>>>();
    hist_kernel<<<(N_EDGES + 255) / 256, 256, 0, s_csr>>>(edge_dst);
    scan_phase1<<<N_SBLOCKS, 256, 0, s_csr>>>();
    scan_phase2<<<1, 128, 0, s_csr>>>();
    scan_phase3<<<N_SBLOCKS, 256, 0, s_csr>>>();
    scatter_kernel<<<(N_EDGES + 255) / 256, 256, 0, s_csr>>>(edge_src, edge_dst, edge_val);
    cudaEventRecord(ev_join, s_csr);

    gemm1_tf32_kernel<<<(N_NODES + G1_BM - 1) / G1_BM, 256, G1_SMEM>>>(x, W1);

    cudaStreamWaitEvent(0, ev_join, 0);

    spmm1_kernel<<<(N_NODES * 32 + 255) / 256, 256>>>(b1);
    gemm2_kernel<<<(N_NODES + 127) / 128, 256, G2_SMEM>>>(W2);
    spmm2_softmax_kernel<<<(N_NODES * 32 + 255) / 256, 256>>>(b2, out);
}

// round 6
// speedup vs baseline: 2.8031x; 1.1953x over previous
#include <cuda_runtime.h>
#include <cuda_fp16.h>
#include <math.h>
#include <stdint.h>

#define N_NODES 100000
#define N_EDGES 1600000
#define NFEAT   512
#define HIDDEN  128
#define NCLASS  40

// ---------------- scratch (device globals; no allocation allowed) ----------
__device__ __half g_support1h[(long)N_NODES * HIDDEN]; // X @ W1 (fp16)
__device__ __half g_h1h[(long)N_NODES * HIDDEN];       // relu(agg + b1) (fp16)
__device__ __half g_support2h[(long)N_NODES * NCLASS]; // h1 @ W2 (fp16)
__device__ int    g_deg[N_NODES];
__device__ int    g_row_ptr[N_NODES + 1];
__device__ int    g_cursor[N_NODES];
__device__ int2   g_edges[N_EDGES];                    // {src, val bits}
__device__ int    g_psum[128];

#define SCAN_TILE 1024
#define N_SBLOCKS ((N_NODES + SCAN_TILE - 1) / SCAN_TILE)   // 98

// ---------------- CSR build --------------------------------------------------
__global__ void zero_deg_kernel() {
    int i = blockIdx.x * blockDim.x + threadIdx.x;
    if (i < N_NODES) g_deg[i] = 0;
}

__global__ void hist_kernel(const int* __restrict__ dst) {
    int i = blockIdx.x * blockDim.x + threadIdx.x;
    if (i < N_EDGES) atomicAdd(&g_deg[dst[i]], 1);
}

__global__ __launch_bounds__(256) void scan_phase1() {
    int b = blockIdx.x, tid = threadIdx.x;
    int lane = tid & 31, warp = tid >> 5;
    int base = b * SCAN_TILE + tid * 4;
    int s = 0;
#pragma unroll
    for (int j = 0; j < 4; j++) {
        int i = base + j;
        if (i < N_NODES) s += g_deg[i];
    }
#pragma unroll
    for (int off = 16; off > 0; off >>= 1)
        s += __shfl_xor_sync(0xFFFFFFFFu, s, off);
    __shared__ int wsum[8];
    if (lane == 0) wsum[warp] = s;
    __syncthreads();
    if (tid == 0) {
        int t = 0;
#pragma unroll
        for (int w = 0; w < 8; w++) t += wsum[w];
        g_psum[b] = t;
    }
}

__global__ __launch_bounds__(128) void scan_phase2() {
    int tid = threadIdx.x;
    __shared__ int sh[128];
    int v = (tid < N_SBLOCKS) ? g_psum[tid] : 0;
    sh[tid] = v;
    __syncthreads();
#pragma unroll
    for (int off = 1; off < 128; off <<= 1) {
        int t = (tid >= off) ? sh[tid - off] : 0;
        __syncthreads();
        sh[tid] += t;
        __syncthreads();
    }
    if (tid < N_SBLOCKS) g_psum[tid] = sh[tid] - v;
}

__global__ __launch_bounds__(256) void scan_phase3() {
    int b = blockIdx.x, tid = threadIdx.x;
    int lane = tid & 31, warp = tid >> 5;
    int base = b * SCAN_TILE + tid * 4;
    int v[4], tsum = 0;
#pragma unroll
    for (int j = 0; j < 4; j++) {
        int i = base + j;
        v[j] = (i < N_NODES) ? g_deg[i] : 0;
        tsum += v[j];
    }
    int incl = tsum;
#pragma unroll
    for (int off = 1; off < 32; off <<= 1) {
        int n = __shfl_up_sync(0xFFFFFFFFu, incl, off);
        if (lane >= off) incl += n;
    }
    __shared__ int wtot[8];
    if (lane == 31) wtot[warp] = incl;
    __syncthreads();
    if (warp == 0 && lane < 8) {
        int wv = wtot[lane];
        int wincl = wv;
#pragma unroll
        for (int off = 1; off < 8; off <<= 1) {
            int n = __shfl_up_sync(0xFFu, wincl, off);
            if (lane >= off) wincl += n;
        }
        wtot[lane] = wincl - wv;
    }
    __syncthreads();
    int run = g_psum[b] + wtot[warp] + incl - tsum;
#pragma unroll
    for (int j = 0; j < 4; j++) {
        int i = base + j;
        if (i < N_NODES) { g_row_ptr[i] = run; g_cursor[i] = run; }
        run += v[j];
    }
    if (b == 0 && tid == 0) g_row_ptr[N_NODES] = N_EDGES;
}

__global__ void scatter_kernel(const int* __restrict__ src,
                               const int* __restrict__ dst,
                               const float* __restrict__ val) {
    int i = blockIdx.x * blockDim.x + threadIdx.x;
    if (i < N_EDGES) {
        int d = dst[i];
        int p = atomicAdd(&g_cursor[d], 1);
        g_edges[p] = make_int2(src[i], __float_as_int(val[i]));
    }
}

// ---------------- GEMM1 (tf32 tensor cores, cp.async double-buffered) -------
#define G1_BM 128
#define G1_BK 32
#define AS_STRIDE 36
#define BS_STRIDE 132
#define AS_WORDS (G1_BM * AS_STRIDE)
#define BS_WORDS (G1_BK * BS_STRIDE)
#define G1_SMEM ((2 * AS_WORDS + 2 * BS_WORDS) * 4)

__device__ __forceinline__ void cp16(uint32_t dst, const void* src, bool pred) {
    int sz = pred ? 16 : 0;
    asm volatile("cp.async.cg.shared.global [%0], [%1], 16, %2;\n"
                 :: "r"(dst), "l"(src), "r"(sz));
}

__device__ __forceinline__ uint32_t rna_tf32(uint32_t raw) {
    uint32_t u;
    asm("cvt.rna.tf32.f32 %0, %1;" : "=r"(u) : "f"(__int_as_float(raw)));
    return u;
}

__global__ __launch_bounds__(256, 2) void gemm1_tf32_kernel(const float* __restrict__ A,
                                                            const float* __restrict__ B) {
    extern __shared__ uint32_t g1sh[];
    uint32_t* As = g1sh;
    uint32_t* Bs = g1sh + 2 * AS_WORDS;
    const uint32_t smem_base = (uint32_t)__cvta_generic_to_shared(g1sh);

    const int tid  = threadIdx.x;
    const int warp = tid >> 5;
    const int lane = tid & 31;
    const int g = lane >> 2;
    const int t = lane & 3;
    const int wm = (warp >> 2) * 64;
    const int wn = (warp & 3) * 32;
    const int block_row = blockIdx.x * G1_BM;

    float acc[4][4][4];
#pragma unroll
    for (int mi = 0; mi < 4; mi++)
#pragma unroll
        for (int ni = 0; ni < 4; ni++)
#pragma unroll
            for (int q = 0; q < 4; q++) acc[mi][ni][q] = 0.f;

    auto load_tile = [&](int buf, int k0) {
#pragma unroll
        for (int j = 0; j < 4; j++) {
            int chunk = tid + j * 256;
            int row = chunk >> 3;
            int col = (chunk & 7) * 4;
            int gr = block_row + row;
            bool ok = gr < N_NODES;
            const float* src = A + (long)(ok ? gr : 0) * NFEAT + k0 + col;
            uint32_t dst = smem_base + (buf * AS_WORDS + row * AS_STRIDE + col) * 4;
            cp16(dst, src, ok);
        }
#pragma unroll
        for (int j = 0; j < 4; j++) {
            int chunk = tid + j * 256;
            int row = chunk >> 5;
            int col = (chunk & 31) * 4;
            const float* src = B + (long)(k0 + row) * HIDDEN + col;
            uint32_t dst = smem_base + (2 * AS_WORDS + buf * BS_WORDS + row * BS_STRIDE + col) * 4;
            cp16(dst, src, true);
        }
    };

    const int NT = NFEAT / G1_BK;
    load_tile(0, 0);
    asm volatile("cp.async.commit_group;\n");

    for (int kt = 0; kt < NT; kt++) {
        int buf = kt & 1;
        if (kt + 1 < NT) {
            load_tile(buf ^ 1, (kt + 1) * G1_BK);
            asm volatile("cp.async.commit_group;\n");
            asm volatile("cp.async.wait_group 1;\n");
        } else {
            asm volatile("cp.async.wait_group 0;\n");
        }
        __syncthreads();

        const uint32_t* Ab = As + buf * AS_WORDS;
        const uint32_t* Bb = Bs + buf * BS_WORDS;
#pragma unroll
        for (int kk = 0; kk < 4; kk++) {
            const int kb = kk * 8;
            uint32_t af[4][4], bf[4][2];
#pragma unroll
            for (int mi = 0; mi < 4; mi++) {
                int r0 = wm + mi * 16 + g;
                af[mi][0] = rna_tf32(Ab[(r0)     * AS_STRIDE + kb + t]);
                af[mi][1] = rna_tf32(Ab[(r0 + 8) * AS_STRIDE + kb + t]);
                af[mi][2] = rna_tf32(Ab[(r0)     * AS_STRIDE + kb + t + 4]);
                af[mi][3] = rna_tf32(Ab[(r0 + 8) * AS_STRIDE + kb + t + 4]);
            }
#pragma unroll
            for (int ni = 0; ni < 4; ni++) {
                int c = wn + ni * 8 + g;
                bf[ni][0] = rna_tf32(Bb[(kb + t)     * BS_STRIDE + c]);
                bf[ni][1] = rna_tf32(Bb[(kb + t + 4) * BS_STRIDE + c]);
            }
#pragma unroll
            for (int mi = 0; mi < 4; mi++) {
#pragma unroll
                for (int ni = 0; ni < 4; ni++) {
                    asm volatile(
                        "mma.sync.aligned.m16n8k8.row.col.f32.tf32.tf32.f32 "
                        "{%0,%1,%2,%3}, {%4,%5,%6,%7}, {%8,%9}, {%0,%1,%2,%3};"
                        : "+f"(acc[mi][ni][0]), "+f"(acc[mi][ni][1]),
                          "+f"(acc[mi][ni][2]), "+f"(acc[mi][ni][3])
                        : "r"(af[mi][0]), "r"(af[mi][1]), "r"(af[mi][2]), "r"(af[mi][3]),
                          "r"(bf[ni][0]), "r"(bf[ni][1]));
                }
            }
        }
        __syncthreads();
    }

#pragma unroll
    for (int mi = 0; mi < 4; mi++) {
        int r0 = block_row + wm + mi * 16 + g;
        int r1 = r0 + 8;
#pragma unroll
        for (int ni = 0; ni < 4; ni++) {
            int c = wn + ni * 8 + 2 * t;
            if (r0 < N_NODES)
                *(__half2*)&g_support1h[(long)r0 * HIDDEN + c] =
                    __floats2half2_rn(acc[mi][ni][0], acc[mi][ni][1]);
            if (r1 < N_NODES)
                *(__half2*)&g_support1h[(long)r1 * HIDDEN + c] =
                    __floats2half2_rn(acc[mi][ni][2], acc[mi][ni][3]);
        }
    }
}

// ---------------- SpMM1: h1h = relu(gather_sum(support1h[src]*val) + b1) ----
__global__ __launch_bounds__(256) void spmm1_kernel(const float* __restrict__ b1) {
    int warp = (blockIdx.x * blockDim.x + threadIdx.x) >> 5;
    int lane = threadIdx.x & 31;
    if (warp >= N_NODES) return;
    int beg = g_row_ptr[warp];
    int end = g_row_ptr[warp + 1];
    float4 acc = make_float4(0.f, 0.f, 0.f, 0.f);
    for (int e = beg; e < end; e++) {
        int2  ed = __ldcs(&g_edges[e]);
        float v  = __int_as_float(ed.y);
        uint2 u = *(const uint2*)&g_support1h[(long)ed.x * HIDDEN + lane * 4];
        float2 f0 = __half22float2(*(__half2*)&u.x);
        float2 f1 = __half22float2(*(__half2*)&u.y);
        acc.x += v * f0.x; acc.y += v * f0.y;
        acc.z += v * f1.x; acc.w += v * f1.y;
    }
    float4 bb = *(const float4*)&b1[lane * 4];
    acc.x = fmaxf(acc.x + bb.x, 0.f);
    acc.y = fmaxf(acc.y + bb.y, 0.f);
    acc.z = fmaxf(acc.z + bb.z, 0.f);
    acc.w = fmaxf(acc.w + bb.w, 0.f);
    uint2 o;
    *(__half2*)&o.x = __floats2half2_rn(acc.x, acc.y);
    *(__half2*)&o.y = __floats2half2_rn(acc.z, acc.w);
    *(uint2*)&g_h1h[(long)warp * HIDDEN + lane * 4] = o;
}

// ---------------- GEMM2 (fp16 tensor cores): support2h = h1h @ W2 -----------
// block: 128 rows, 8 warps; warp: 16 rows x 40 cols; m16n8k16, K=128 (8 steps)
#define H_STRIDE 136   // halves; (g*68+t) words mod 32 distinct -> conflict-free
#define G2H_SMEM ((128 * H_STRIDE + 40 * H_STRIDE) * 2)

__global__ __launch_bounds__(256) void gemm2_h_kernel(const float* __restrict__ W2) {
    extern __shared__ __half sh2[];
    __half* shH = sh2;                    // [128][H_STRIDE]
    __half* shW = sh2 + 128 * H_STRIDE;   // [40][H_STRIDE]  (n-major: shW[n][k])
    const int tid  = threadIdx.x;
    const int warp = tid >> 5;
    const int lane = tid & 31;
    const int g = lane >> 2;
    const int t = lane & 3;
    const int row0 = blockIdx.x * 128;

    // load h1h tile: 128 rows x 128 halves, 8B chunks (4 halves)... use 16B (8 halves)
#pragma unroll
    for (int j = 0; j < 8; j++) {
        int chunk = tid + j * 256;         // 2048 chunks of 8 halves
        int r = chunk >> 4;
        int c8 = (chunk & 15) * 8;
        uint4 v = make_uint4(0, 0, 0, 0);
        if (row0 + r < N_NODES)
            v = *(const uint4*)&g_h1h[(long)(row0 + r) * HIDDEN + c8];
        *(uint4*)&shH[r * H_STRIDE + c8] = v;
    }
    // load W2 fp32 -> fp16 transposed (shW[n][k])
    for (int e = tid; e < HIDDEN * NCLASS; e += 256) {
        int k = e / NCLASS, n = e % NCLASS;
        shW[n * H_STRIDE + k] = __float2half_rn(W2[e]);
    }
    __syncthreads();

    const int wm = warp * 16;
    float acc[5][4];
#pragma unroll
    for (int n = 0; n < 5; n++)
#pragma unroll
        for (int q = 0; q < 4; q++) acc[n][q] = 0.f;

#pragma unroll
    for (int ks = 0; ks < 8; ks++) {
        const int k0 = ks * 16;
        uint32_t a0 = *(uint32_t*)&shH[(wm + g)     * H_STRIDE + k0 + 2 * t];
        uint32_t a1 = *(uint32_t*)&shH[(wm + g + 8) * H_STRIDE + k0 + 2 * t];
        uint32_t a2 = *(uint32_t*)&shH[(wm + g)     * H_STRIDE + k0 + 8 + 2 * t];
        uint32_t a3 = *(uint32_t*)&shH[(wm + g + 8) * H_STRIDE + k0 + 8 + 2 * t];
#pragma unroll
        for (int n = 0; n < 5; n++) {
            uint32_t b0 = *(uint32_t*)&shW[(n * 8 + g) * H_STRIDE + k0 + 2 * t];
            uint32_t b1 = *(uint32_t*)&shW[(n * 8 + g) * H_STRIDE + k0 + 8 + 2 * t];
            asm volatile(
                "mma.sync.aligned.m16n8k16.row.col.f32.f16.f16.f32 "
                "{%0,%1,%2,%3}, {%4,%5,%6,%7}, {%8,%9}, {%0,%1,%2,%3};"
                : "+f"(acc[n][0]), "+f"(acc[n][1]), "+f"(acc[n][2]), "+f"(acc[n][3])
                : "r"(a0), "r"(a1), "r"(a2), "r"(a3), "r"(b0), "r"(b1));
        }
    }

    // store: c0=(g,2t) c1=(g,2t+1) c2=(g+8,2t) c3=(g+8,2t+1) per n-tile
#pragma unroll
    for (int n = 0; n < 5; n++) {
        int c = n * 8 + 2 * t;
        int r0 = row0 + wm + g;
        int r1 = r0 + 8;
        if (r0 < N_NODES)
            *(__half2*)&g_support2h[(long)r0 * NCLASS + c] =
                __floats2half2_rn(acc[n][0], acc[n][1]);
        if (r1 < N_NODES)
            *(__half2*)&g_support2h[(long)r1 * NCLASS + c] =
                __floats2half2_rn(acc[n][2], acc[n][3]);
    }
}

// ---------------- SpMM2 + bias + log_softmax --------------------------------
// lane < 20 owns classes {2*lane, 2*lane+1}
__global__ __launch_bounds__(256) void spmm2_softmax_kernel(const float* __restrict__ b2,
                                                            float* __restrict__ out) {
    int warp = (blockIdx.x * blockDim.x + threadIdx.x) >> 5;
    int lane = threadIdx.x & 31;
    if (warp >= N_NODES) return;
    int beg = g_row_ptr[warp];
    int end = g_row_ptr[warp + 1];
    bool act = lane < 20;
    float a0 = 0.f, a1 = 0.f;
    for (int e = beg; e < end; e++) {
        int2  ed = __ldcs(&g_edges[e]);
        float v  = __int_as_float(ed.y);
        if (act) {
            uint32_t u = *(const uint32_t*)&g_support2h[(long)ed.x * NCLASS + 2 * lane];
            float2 f = __half22float2(*(__half2*)&u);
            a0 += v * f.x;
            a1 += v * f.y;
        }
    }
    float z0 = -INFINITY, z1 = -INFINITY;
    if (act) {
        z0 = a0 + b2[2 * lane];
        z1 = a1 + b2[2 * lane + 1];
    }
    float m = fmaxf(z0, z1);
#pragma unroll
    for (int off = 16; off > 0; off >>= 1)
        m = fmaxf(m, __shfl_xor_sync(0xFFFFFFFFu, m, off));
    float s = act ? (expf(z0 - m) + expf(z1 - m)) : 0.f;
#pragma unroll
    for (int off = 16; off > 0; off >>= 1)
        s += __shfl_xor_sync(0xFFFFFFFFu, s, off);
    float L = m + logf(s);
    if (act)
        *(float2*)&out[(long)warp * NCLASS + 2 * lane] = make_float2(z0 - L, z1 - L);
}

// ---------------- launch -----------------------------------------------------
extern "C" void kernel_launch(void* const* d_in, const int* in_sizes, int n_in,
                              void* d_out, int out_size) {
    const float* x        = (const float*)d_in[0];
    const int*   edge_src = (const int*)d_in[1];
    const int*   edge_dst = (const int*)d_in[2];
    const float* edge_val = (const float*)d_in[3];
    const float* W1       = (const float*)d_in[4];
    const float* b1       = (const float*)d_in[5];
    const float* W2       = (const float*)d_in[6];
    const float* b2       = (const float*)d_in[7];
    float* out = (float*)d_out;

    (void)in_sizes; (void)n_in; (void)out_size;

    static cudaStream_t s_csr = nullptr;
    static cudaEvent_t  ev_fork = nullptr, ev_join = nullptr;
    static bool s_init = false;
    if (!s_init) {
        cudaStreamCreateWithFlags(&s_csr, cudaStreamNonBlocking);
        cudaEventCreateWithFlags(&ev_fork, cudaEventDisableTiming);
        cudaEventCreateWithFlags(&ev_join, cudaEventDisableTiming);
        cudaFuncSetAttribute(gemm1_tf32_kernel, cudaFuncAttributeMaxDynamicSharedMemorySize, G1_SMEM);
        cudaFuncSetAttribute(gemm2_h_kernel, cudaFuncAttributeMaxDynamicSharedMemorySize, G2H_SMEM);
        s_init = true;
    }

    cudaEventRecord(ev_fork, 0);
    cudaStreamWaitEvent(s_csr, ev_fork, 0);

    zero_deg_kernel<<<(N_NODES + 255) / 256, 256, 0, s_csr>>>();
    hist_kernel<<<(N_EDGES + 255) / 256, 256, 0, s_csr>>>(edge_dst);
    scan_phase1<<<N_SBLOCKS, 256, 0, s_csr>>>();
    scan_phase2<<<1, 128, 0, s_csr>>>();
    scan_phase3<<<N_SBLOCKS, 256, 0, s_csr>>>();
    scatter_kernel<<<(N_EDGES + 255) / 256, 256, 0, s_csr>>>(edge_src, edge_dst, edge_val);
    cudaEventRecord(ev_join, s_csr);

    gemm1_tf32_kernel<<<(N_NODES + G1_BM - 1) / G1_BM, 256, G1_SMEM>>>(x, W1);

    cudaStreamWaitEvent(0, ev_join, 0);

    spmm1_kernel<<<(N_NODES * 32 + 255) / 256, 256>>>(b1);
    gemm2_h_kernel<<<(N_NODES + 127) / 128, 256, G2H_SMEM>>>(W2);
    spmm2_softmax_kernel<<<(N_NODES * 32 + 255) / 256, 256>>>(b2, out);
}

// round 7
// speedup vs baseline: 3.1971x; 1.1405x over previous
#include <cuda_runtime.h>
#include <cuda_fp16.h>
#include <math.h>
#include <stdint.h>

#define N_NODES 100000
#define N_EDGES 1600000
#define NFEAT   512
#define HIDDEN  128
#define NCLASS  40

// ---------------- scratch (device globals; no allocation allowed) ----------
__device__ __half g_support1h[(long)N_NODES * HIDDEN]; // X @ W1 (fp16)
__device__ __half g_h1h[(long)N_NODES * HIDDEN];       // relu(agg + b1) (fp16)
__device__ __half g_support2h[(long)N_NODES * NCLASS]; // h1 @ W2 (fp16)
__device__ __half g_W1t[(long)NFEAT * HIDDEN];         // W1^T fp16 [n][k]
__device__ int    g_deg[N_NODES];
__device__ int    g_row_ptr[N_NODES + 1];
__device__ int    g_cursor[N_NODES];
__device__ int2   g_edges[N_EDGES];                    // {src, val bits}
__device__ int    g_psum[128];

#define SCAN_TILE 1024
#define N_SBLOCKS ((N_NODES + SCAN_TILE - 1) / SCAN_TILE)   // 98

// ---------------- CSR build --------------------------------------------------
__global__ void zero_deg_kernel() {
    int i = blockIdx.x * blockDim.x + threadIdx.x;
    if (i < N_NODES) g_deg[i] = 0;
}

__global__ void hist_kernel(const int* __restrict__ dst) {
    int i = blockIdx.x * blockDim.x + threadIdx.x;
    if (i < N_EDGES) atomicAdd(&g_deg[dst[i]], 1);
}

__global__ __launch_bounds__(256) void scan_phase1() {
    int b = blockIdx.x, tid = threadIdx.x;
    int lane = tid & 31, warp = tid >> 5;
    int base = b * SCAN_TILE + tid * 4;
    int s = 0;
#pragma unroll
    for (int j = 0; j < 4; j++) {
        int i = base + j;
        if (i < N_NODES) s += g_deg[i];
    }
#pragma unroll
    for (int off = 16; off > 0; off >>= 1)
        s += __shfl_xor_sync(0xFFFFFFFFu, s, off);
    __shared__ int wsum[8];
    if (lane == 0) wsum[warp] = s;
    __syncthreads();
    if (tid == 0) {
        int t = 0;
#pragma unroll
        for (int w = 0; w < 8; w++) t += wsum[w];
        g_psum[b] = t;
    }
}

__global__ __launch_bounds__(128) void scan_phase2() {
    int tid = threadIdx.x;
    __shared__ int sh[128];
    int v = (tid < N_SBLOCKS) ? g_psum[tid] : 0;
    sh[tid] = v;
    __syncthreads();
#pragma unroll
    for (int off = 1; off < 128; off <<= 1) {
        int t = (tid >= off) ? sh[tid - off] : 0;
        __syncthreads();
        sh[tid] += t;
        __syncthreads();
    }
    if (tid < N_SBLOCKS) g_psum[tid] = sh[tid] - v;
}

__global__ __launch_bounds__(256) void scan_phase3() {
    int b = blockIdx.x, tid = threadIdx.x;
    int lane = tid & 31, warp = tid >> 5;
    int base = b * SCAN_TILE + tid * 4;
    int v[4], tsum = 0;
#pragma unroll
    for (int j = 0; j < 4; j++) {
        int i = base + j;
        v[j] = (i < N_NODES) ? g_deg[i] : 0;
        tsum += v[j];
    }
    int incl = tsum;
#pragma unroll
    for (int off = 1; off < 32; off <<= 1) {
        int n = __shfl_up_sync(0xFFFFFFFFu, incl, off);
        if (lane >= off) incl += n;
    }
    __shared__ int wtot[8];
    if (lane == 31) wtot[warp] = incl;
    __syncthreads();
    if (warp == 0 && lane < 8) {
        int wv = wtot[lane];
        int wincl = wv;
#pragma unroll
        for (int off = 1; off < 8; off <<= 1) {
            int n = __shfl_up_sync(0xFFu, wincl, off);
            if (lane >= off) wincl += n;
        }
        wtot[lane] = wincl - wv;
    }
    __syncthreads();
    int run = g_psum[b] + wtot[warp] + incl - tsum;
#pragma unroll
    for (int j = 0; j < 4; j++) {
        int i = base + j;
        if (i < N_NODES) { g_row_ptr[i] = run; g_cursor[i] = run; }
        run += v[j];
    }
    if (b == 0 && tid == 0) g_row_ptr[N_NODES] = N_EDGES;
}

__global__ void scatter_kernel(const int* __restrict__ src,
                               const int* __restrict__ dst,
                               const float* __restrict__ val) {
    int i = blockIdx.x * blockDim.x + threadIdx.x;
    if (i < N_EDGES) {
        int d = dst[i];
        int p = atomicAdd(&g_cursor[d], 1);
        g_edges[p] = make_int2(src[i], __float_as_int(val[i]));
    }
}

// ---------------- W1 transpose + fp16 convert --------------------------------
__global__ __launch_bounds__(256) void w1t_kernel(const float* __restrict__ W1) {
    int i = blockIdx.x * blockDim.x + threadIdx.x;   // over NFEAT*HIDDEN
    if (i < NFEAT * HIDDEN) {
        int k = i / HIDDEN, n = i % HIDDEN;
        g_W1t[(long)n * NFEAT + k] = __float2half_rn(W1[i]);
    }
}

// ---------------- GEMM1 (fp16 tensor cores, reg-staged A + cp.async B) ------
// support1h = X[100000,512] @ W1[512,128]
// block 128x128, BK=32, 8 warps, warp 64x32, m16n8k16.
#define G1_BM 128
#define G1_BK 32
#define HSTR 40          // halves stride; word stride 20 -> conflict-free frags

__device__ __forceinline__ void cp16b(uint32_t dst, const void* src) {
    asm volatile("cp.async.cg.shared.global [%0], [%1], 16;\n"
                 :: "r"(dst), "l"(src));
}

__global__ __launch_bounds__(256, 2) void gemm1_f16_kernel(const float* __restrict__ A) {
    __shared__ __half Ah[2][G1_BM * HSTR];   // [row][k]
    __shared__ __half Bh[2][HIDDEN * HSTR];  // [n][k]

    const int tid  = threadIdx.x;
    const int warp = tid >> 5;
    const int lane = tid & 31;
    const int g = lane >> 2;
    const int t = lane & 3;
    const int wm = (warp >> 2) * 64;
    const int wn = (warp & 3) * 32;
    const int block_row = blockIdx.x * G1_BM;

    // A staging: 1024 float4 chunks per tile, 4 per thread
    const int a_row = tid >> 1;             // rows covered twice (2 chunks/row)... no:
    // chunk mapping: chunk = tid + j*256; row = chunk>>3 (0..127), col=(chunk&7)*4
    float4 areg[4];
    const int b_n0 = tid >> 2;              // B: chunk = tid + j*256; n = chunk>>2, kc=(chunk&3)*8
    (void)a_row; (void)b_n0;

    float acc[4][4][4];
#pragma unroll
    for (int mi = 0; mi < 4; mi++)
#pragma unroll
        for (int ni = 0; ni < 4; ni++)
#pragma unroll
            for (int q = 0; q < 4; q++) acc[mi][ni][q] = 0.f;

    auto ldgA = [&](int k0) {
#pragma unroll
        for (int j = 0; j < 4; j++) {
            int chunk = tid + j * 256;
            int row = chunk >> 3;
            int col = (chunk & 7) * 4;
            int gr = block_row + row;
            if (gr < N_NODES)
                areg[j] = *(const float4*)&A[(long)gr * NFEAT + k0 + col];
            else
                areg[j] = make_float4(0.f, 0.f, 0.f, 0.f);
        }
    };
    auto stsA = [&](int buf) {
#pragma unroll
        for (int j = 0; j < 4; j++) {
            int chunk = tid + j * 256;
            int row = chunk >> 3;
            int col = (chunk & 7) * 4;
            uint2 h;
            *(__half2*)&h.x = __floats2half2_rn(areg[j].x, areg[j].y);
            *(__half2*)&h.y = __floats2half2_rn(areg[j].z, areg[j].w);
            *(uint2*)&Ah[buf][row * HSTR + col] = h;
        }
    };
    auto cpB = [&](int buf, int k0) {
        uint32_t base = (uint32_t)__cvta_generic_to_shared(&Bh[buf][0]);
#pragma unroll
        for (int j = 0; j < 2; j++) {
            int chunk = tid + j * 256;
            int n = chunk >> 2;
            int kc = (chunk & 3) * 8;
            cp16b(base + (n * HSTR + kc) * 2, &g_W1t[(long)n * NFEAT + k0 + kc]);
        }
    };

    const int NT = NFEAT / G1_BK;   // 16
    ldgA(0);
    cpB(0, 0);
    asm volatile("cp.async.commit_group;\n");

    for (int kt = 0; kt < NT; kt++) {
        int buf = kt & 1;
        stsA(buf);                       // convert tile kt from regs
        if (kt + 1 < NT) {
            ldgA((kt + 1) * G1_BK);      // prefetch A tile kt+1 into regs
            cpB(buf ^ 1, (kt + 1) * G1_BK);
            asm volatile("cp.async.commit_group;\n");
            asm volatile("cp.async.wait_group 1;\n");
        } else {
            asm volatile("cp.async.wait_group 0;\n");
        }
        __syncthreads();

#pragma unroll
        for (int ks = 0; ks < 2; ks++) {
            const int kb = ks * 16;
            uint32_t af[4][4], bf[4][2];
#pragma unroll
            for (int mi = 0; mi < 4; mi++) {
                int r0 = wm + mi * 16 + g;
                af[mi][0] = *(uint32_t*)&Ah[buf][(r0)     * HSTR + kb + 2 * t];
                af[mi][1] = *(uint32_t*)&Ah[buf][(r0 + 8) * HSTR + kb + 2 * t];
                af[mi][2] = *(uint32_t*)&Ah[buf][(r0)     * HSTR + kb + 8 + 2 * t];
                af[mi][3] = *(uint32_t*)&Ah[buf][(r0 + 8) * HSTR + kb + 8 + 2 * t];
            }
#pragma unroll
            for (int ni = 0; ni < 4; ni++) {
                int c = wn + ni * 8 + g;
                bf[ni][0] = *(uint32_t*)&Bh[buf][c * HSTR + kb + 2 * t];
                bf[ni][1] = *(uint32_t*)&Bh[buf][c * HSTR + kb + 8 + 2 * t];
            }
#pragma unroll
            for (int mi = 0; mi < 4; mi++) {
#pragma unroll
                for (int ni = 0; ni < 4; ni++) {
                    asm volatile(
                        "mma.sync.aligned.m16n8k16.row.col.f32.f16.f16.f32 "
                        "{%0,%1,%2,%3}, {%4,%5,%6,%7}, {%8,%9}, {%0,%1,%2,%3};"
                        : "+f"(acc[mi][ni][0]), "+f"(acc[mi][ni][1]),
                          "+f"(acc[mi][ni][2]), "+f"(acc[mi][ni][3])
                        : "r"(af[mi][0]), "r"(af[mi][1]), "r"(af[mi][2]), "r"(af[mi][3]),
                          "r"(bf[ni][0]), "r"(bf[ni][1]));
                }
            }
        }
        __syncthreads();
    }

#pragma unroll
    for (int mi = 0; mi < 4; mi++) {
        int r0 = block_row + wm + mi * 16 + g;
        int r1 = r0 + 8;
#pragma unroll
        for (int ni = 0; ni < 4; ni++) {
            int c = wn + ni * 8 + 2 * t;
            if (r0 < N_NODES)
                *(__half2*)&g_support1h[(long)r0 * HIDDEN + c] =
                    __floats2half2_rn(acc[mi][ni][0], acc[mi][ni][1]);
            if (r1 < N_NODES)
                *(__half2*)&g_support1h[(long)r1 * HIDDEN + c] =
                    __floats2half2_rn(acc[mi][ni][2], acc[mi][ni][3]);
        }
    }
}

// ---------------- SpMM1: h1h = relu(gather_sum(support1h[src]*val) + b1) ----
__global__ __launch_bounds__(256) void spmm1_kernel(const float* __restrict__ b1) {
    int warp = (blockIdx.x * blockDim.x + threadIdx.x) >> 5;
    int lane = threadIdx.x & 31;
    if (warp >= N_NODES) return;
    int beg = g_row_ptr[warp];
    int end = g_row_ptr[warp + 1];
    float4 acc = make_float4(0.f, 0.f, 0.f, 0.f);
    for (int e = beg; e < end; e++) {
        int2  ed = __ldcs(&g_edges[e]);
        float v  = __int_as_float(ed.y);
        uint2 u = *(const uint2*)&g_support1h[(long)ed.x * HIDDEN + lane * 4];
        float2 f0 = __half22float2(*(__half2*)&u.x);
        float2 f1 = __half22float2(*(__half2*)&u.y);
        acc.x += v * f0.x; acc.y += v * f0.y;
        acc.z += v * f1.x; acc.w += v * f1.y;
    }
    float4 bb = *(const float4*)&b1[lane * 4];
    acc.x = fmaxf(acc.x + bb.x, 0.f);
    acc.y = fmaxf(acc.y + bb.y, 0.f);
    acc.z = fmaxf(acc.z + bb.z, 0.f);
    acc.w = fmaxf(acc.w + bb.w, 0.f);
    uint2 o;
    *(__half2*)&o.x = __floats2half2_rn(acc.x, acc.y);
    *(__half2*)&o.y = __floats2half2_rn(acc.z, acc.w);
    *(uint2*)&g_h1h[(long)warp * HIDDEN + lane * 4] = o;
}

// ---------------- GEMM2 (fp16 tensor cores): support2h = h1h @ W2 -----------
#define H_STRIDE 136
#define G2H_SMEM ((128 * H_STRIDE + 40 * H_STRIDE) * 2)

__global__ __launch_bounds__(256) void gemm2_h_kernel(const float* __restrict__ W2) {
    extern __shared__ __half sh2[];
    __half* shH = sh2;                    // [128][H_STRIDE]
    __half* shW = sh2 + 128 * H_STRIDE;   // [40][H_STRIDE]
    const int tid  = threadIdx.x;
    const int warp = tid >> 5;
    const int lane = tid & 31;
    const int g = lane >> 2;
    const int t = lane & 3;
    const int row0 = blockIdx.x * 128;

#pragma unroll
    for (int j = 0; j < 8; j++) {
        int chunk = tid + j * 256;
        int r = chunk >> 4;
        int c8 = (chunk & 15) * 8;
        uint4 v = make_uint4(0, 0, 0, 0);
        if (row0 + r < N_NODES)
            v = *(const uint4*)&g_h1h[(long)(row0 + r) * HIDDEN + c8];
        *(uint4*)&shH[r * H_STRIDE + c8] = v;
    }
    for (int e = tid; e < HIDDEN * NCLASS; e += 256) {
        int k = e / NCLASS, n = e % NCLASS;
        shW[n * H_STRIDE + k] = __float2half_rn(W2[e]);
    }
    __syncthreads();

    const int wm = warp * 16;
    float acc[5][4];
#pragma unroll
    for (int n = 0; n < 5; n++)
#pragma unroll
        for (int q = 0; q < 4; q++) acc[n][q] = 0.f;

#pragma unroll
    for (int ks = 0; ks < 8; ks++) {
        const int k0 = ks * 16;
        uint32_t a0 = *(uint32_t*)&shH[(wm + g)     * H_STRIDE + k0 + 2 * t];
        uint32_t a1 = *(uint32_t*)&shH[(wm + g + 8) * H_STRIDE + k0 + 2 * t];
        uint32_t a2 = *(uint32_t*)&shH[(wm + g)     * H_STRIDE + k0 + 8 + 2 * t];
        uint32_t a3 = *(uint32_t*)&shH[(wm + g + 8) * H_STRIDE + k0 + 8 + 2 * t];
#pragma unroll
        for (int n = 0; n < 5; n++) {
            uint32_t b0 = *(uint32_t*)&shW[(n * 8 + g) * H_STRIDE + k0 + 2 * t];
            uint32_t b1 = *(uint32_t*)&shW[(n * 8 + g) * H_STRIDE + k0 + 8 + 2 * t];
            asm volatile(
                "mma.sync.aligned.m16n8k16.row.col.f32.f16.f16.f32 "
                "{%0,%1,%2,%3}, {%4,%5,%6,%7}, {%8,%9}, {%0,%1,%2,%3};"
                : "+f"(acc[n][0]), "+f"(acc[n][1]), "+f"(acc[n][2]), "+f"(acc[n][3])
                : "r"(a0), "r"(a1), "r"(a2), "r"(a3), "r"(b0), "r"(b1));
        }
    }

#pragma unroll
    for (int n = 0; n < 5; n++) {
        int c = n * 8 + 2 * t;
        int r0 = row0 + wm + g;
        int r1 = r0 + 8;
        if (r0 < N_NODES)
            *(__half2*)&g_support2h[(long)r0 * NCLASS + c] =
                __floats2half2_rn(acc[n][0], acc[n][1]);
        if (r1 < N_NODES)
            *(__half2*)&g_support2h[(long)r1 * NCLASS + c] =
                __floats2half2_rn(acc[n][2], acc[n][3]);
    }
}

// ---------------- SpMM2 + bias + log_softmax --------------------------------
__global__ __launch_bounds__(256) void spmm2_softmax_kernel(const float* __restrict__ b2,
                                                            float* __restrict__ out) {
    int warp = (blockIdx.x * blockDim.x + threadIdx.x) >> 5;
    int lane = threadIdx.x & 31;
    if (warp >= N_NODES) return;
    int beg = g_row_ptr[warp];
    int end = g_row_ptr[warp + 1];
    bool act = lane < 20;
    float a0 = 0.f, a1 = 0.f;
    for (int e = beg; e < end; e++) {
        int2  ed = __ldcs(&g_edges[e]);
        float v  = __int_as_float(ed.y);
        if (act) {
            uint32_t u = *(const uint32_t*)&g_support2h[(long)ed.x * NCLASS + 2 * lane];
            float2 f = __half22float2(*(__half2*)&u);
            a0 += v * f.x;
            a1 += v * f.y;
        }
    }
    float z0 = -INFINITY, z1 = -INFINITY;
    if (act) {
        z0 = a0 + b2[2 * lane];
        z1 = a1 + b2[2 * lane + 1];
    }
    float m = fmaxf(z0, z1);
#pragma unroll
    for (int off = 16; off > 0; off >>= 1)
        m = fmaxf(m, __shfl_xor_sync(0xFFFFFFFFu, m, off));
    float s = act ? (expf(z0 - m) + expf(z1 - m)) : 0.f;
#pragma unroll
    for (int off = 16; off > 0; off >>= 1)
        s += __shfl_xor_sync(0xFFFFFFFFu, s, off);
    float L = m + logf(s);
    if (act)
        *(float2*)&out[(long)warp * NCLASS + 2 * lane] = make_float2(z0 - L, z1 - L);
}

// ---------------- launch -----------------------------------------------------
extern "C" void kernel_launch(void* const* d_in, const int* in_sizes, int n_in,
                              void* d_out, int out_size) {
    const float* x        = (const float*)d_in[0];
    const int*   edge_src = (const int*)d_in[1];
    const int*   edge_dst = (const int*)d_in[2];
    const float* edge_val = (const float*)d_in[3];
    const float* W1       = (const float*)d_in[4];
    const float* b1       = (const float*)d_in[5];
    const float* W2       = (const float*)d_in[6];
    const float* b2       = (const float*)d_in[7];
    float* out = (float*)d_out;

    (void)in_sizes; (void)n_in; (void)out_size;

    static cudaStream_t s_csr = nullptr;
    static cudaEvent_t  ev_fork = nullptr, ev_join = nullptr;
    static bool s_init = false;
    if (!s_init) {
        cudaStreamCreateWithFlags(&s_csr, cudaStreamNonBlocking);
        cudaEventCreateWithFlags(&ev_fork, cudaEventDisableTiming);
        cudaEventCreateWithFlags(&ev_join, cudaEventDisableTiming);
        cudaFuncSetAttribute(gemm2_h_kernel, cudaFuncAttributeMaxDynamicSharedMemorySize, G2H_SMEM);
        s_init = true;
    }

    cudaEventRecord(ev_fork, 0);
    cudaStreamWaitEvent(s_csr, ev_fork, 0);

    zero_deg_kernel<<<(N_NODES + 255) / 256, 256, 0, s_csr>>>();
    hist_kernel<<<(N_EDGES + 255) / 256, 256, 0, s_csr>>>(edge_dst);
    scan_phase1<<<N_SBLOCKS, 256, 0, s_csr>>>();
    scan_phase2<<<1, 128, 0, s_csr>>>();
    scan_phase3<<<N_SBLOCKS, 256, 0, s_csr>>>();
    scatter_kernel<<<(N_EDGES + 255) / 256, 256, 0, s_csr>>>(edge_src, edge_dst, edge_val);
    cudaEventRecord(ev_join, s_csr);

    // main stream: W1 transpose then fp16 GEMM1
    w1t_kernel<<<(NFEAT * HIDDEN + 255) / 256, 256>>>(W1);
    gemm1_f16_kernel<<<(N_NODES + G1_BM - 1) / G1_BM, 256>>>(x);

    cudaStreamWaitEvent(0, ev_join, 0);

    spmm1_kernel<<<(N_NODES * 32 + 255) / 256, 256>>>(b1);
    gemm2_h_kernel<<<(N_NODES + 127) / 128, 256, G2H_SMEM>>>(W2);
    spmm2_softmax_kernel<<<(N_NODES * 32 + 255) / 256, 256>>>(b2, out);
}